// round 3
// baseline (speedup 1.0000x reference)
#include <cuda_runtime.h>
#include <cooperative_groups.h>
#include <math.h>

namespace cg = cooperative_groups;

#define Bq   4
#define Tq   2048
#define INq  64
#define Hq   256
#define Dq   512
#define G4q  1024
#define EPSq 1e-5f

// ---------------- static scratch ----------------
__device__ float g_gx0[Bq * Tq * G4q];
__device__ float g_gx1[Bq * Tq * G4q];
__device__ float g_h1 [Bq * Tq * Hq];
__device__ float g_h2 [Bq * Tq * Hq];
__device__ float g_cv [Bq * Tq * Hq];
__device__ float g_kv [Bq * Tq * G4q];
__device__ float g_at [Bq * Dq];

__device__ __forceinline__ float sigp(float x) { return 1.f / (1.f + expf(-x)); }

// ---------------- GEMM: out[m,n] = sum_k A[m,k]*W[n,k] + b1[n] (+ b2[n]) ---------
// A split at Ksplit between A1/A2 (concat along k).
__global__ __launch_bounds__(256) void gemm64(
    const float* __restrict__ A1, const float* __restrict__ A2,
    int Ksplit, int K,
    const float* __restrict__ W, const float* __restrict__ b1,
    const float* __restrict__ b2, float* __restrict__ out, int N)
{
    __shared__ float As[16][64];
    __shared__ float Bs[16][64];
    const int m0 = blockIdx.x * 64, n0 = blockIdx.y * 64;
    const int tid = threadIdx.x;
    const int tx = tid & 15, ty = tid >> 4;
    const int lm = tid >> 2;
    const int lk4 = (tid & 3) * 4;
    const int K2 = K - Ksplit;

    float acc[4][4];
#pragma unroll
    for (int i = 0; i < 4; i++)
#pragma unroll
        for (int j = 0; j < 4; j++) acc[i][j] = 0.f;

    for (int k0 = 0; k0 < K; k0 += 16) {
        {
            int m = m0 + lm;
            int kg = k0 + lk4;
            float4 v;
            if (kg < Ksplit) v = *(const float4*)(A1 + (size_t)m * Ksplit + kg);
            else             v = *(const float4*)(A2 + (size_t)m * K2 + (kg - Ksplit));
            As[lk4 + 0][lm] = v.x; As[lk4 + 1][lm] = v.y;
            As[lk4 + 2][lm] = v.z; As[lk4 + 3][lm] = v.w;
            int n = n0 + lm;
            float4 wv = *(const float4*)(W + (size_t)n * K + k0 + lk4);
            Bs[lk4 + 0][lm] = wv.x; Bs[lk4 + 1][lm] = wv.y;
            Bs[lk4 + 2][lm] = wv.z; Bs[lk4 + 3][lm] = wv.w;
        }
        __syncthreads();
#pragma unroll
        for (int kk = 0; kk < 16; kk++) {
            float4 a = *(const float4*)&As[kk][ty * 4];
            float4 b = *(const float4*)&Bs[kk][tx * 4];
            acc[0][0] = fmaf(a.x, b.x, acc[0][0]); acc[0][1] = fmaf(a.x, b.y, acc[0][1]);
            acc[0][2] = fmaf(a.x, b.z, acc[0][2]); acc[0][3] = fmaf(a.x, b.w, acc[0][3]);
            acc[1][0] = fmaf(a.y, b.x, acc[1][0]); acc[1][1] = fmaf(a.y, b.y, acc[1][1]);
            acc[1][2] = fmaf(a.y, b.z, acc[1][2]); acc[1][3] = fmaf(a.y, b.w, acc[1][3]);
            acc[2][0] = fmaf(a.z, b.x, acc[2][0]); acc[2][1] = fmaf(a.z, b.y, acc[2][1]);
            acc[2][2] = fmaf(a.z, b.z, acc[2][2]); acc[2][3] = fmaf(a.z, b.w, acc[2][3]);
            acc[3][0] = fmaf(a.w, b.x, acc[3][0]); acc[3][1] = fmaf(a.w, b.y, acc[3][1]);
            acc[3][2] = fmaf(a.w, b.z, acc[3][2]); acc[3][3] = fmaf(a.w, b.w, acc[3][3]);
        }
        __syncthreads();
    }

    float bias[4];
#pragma unroll
    for (int j = 0; j < 4; j++) {
        int n = n0 + tx * 4 + j;
        bias[j] = b1[n] + (b2 ? b2[n] : 0.f);
    }
#pragma unroll
    for (int i = 0; i < 4; i++) {
        int m = m0 + ty * 4 + i;
        float4 r = make_float4(acc[i][0] + bias[0], acc[i][1] + bias[1],
                               acc[i][2] + bias[2], acc[i][3] + bias[3]);
        *(float4*)(out + (size_t)m * N + n0 + tx * 4) = r;
    }
}

// ---------------- conv1d(K=5,same) + BN + SiLU ----------------
// grid (T/32, H/64, B), 256 threads, dynamic smem.
__global__ __launch_bounds__(256, 1) void conv_bn_silu(
    const float* __restrict__ x, const float* __restrict__ cw,
    const float* __restrict__ cb, const float* __restrict__ bg,
    const float* __restrict__ bnb, const float* __restrict__ bmean,
    const float* __restrict__ bvar)
{
    extern __shared__ float sm[];
    float* xs = sm;              // [36][64]
    float* ws = sm + 36 * 64;    // [64][321]
    const int b = blockIdx.z;
    const int t0 = blockIdx.x * 32;
    const int ocb = blockIdx.y * 64;
    const int tid = threadIdx.x;

    for (int idx = tid; idx < 36 * 64; idx += 256) {
        int tr = idx >> 6, i = idx & 63;
        int tg = t0 + tr - 2;
        xs[idx] = (tg >= 0 && tg < Tq) ? x[((size_t)b * Tq + tg) * INq + i] : 0.f;
    }
    for (int idx = tid; idx < 64 * 320; idx += 256) {
        int o = idx / 320, ik = idx % 320;
        ws[o * 321 + ik] = cw[(size_t)(ocb + o) * 320 + ik];
    }
    __syncthreads();

    const int o = tid & 63, gq = tid >> 6;
    const int tb = gq * 8;
    float acc[8];
#pragma unroll
    for (int t = 0; t < 8; t++) acc[t] = 0.f;

    for (int i = 0; i < 64; i++) {
        float xv[12];
#pragma unroll
        for (int j = 0; j < 12; j++) xv[j] = xs[(tb + j) * 64 + i];
#pragma unroll
        for (int k = 0; k < 5; k++) {
            float wv = ws[o * 321 + i * 5 + k];
#pragma unroll
            for (int t = 0; t < 8; t++) acc[t] = fmaf(xv[t + k], wv, acc[t]);
        }
    }
    const int oc = ocb + o;
    float scl = rsqrtf(bvar[oc] + EPSq) * bg[oc];
    float sh = bnb[oc] - bmean[oc] * scl;
    float cbv = cb[oc];
#pragma unroll
    for (int t = 0; t < 8; t++) {
        float y = (acc[t] + cbv) * scl + sh;
        g_cv[((size_t)b * Tq + t0 + tb + t) * Hq + oc] = y / (1.f + __expf(-y));
    }
}

// ---------------- LSTM scan: 8-CTA cluster ----------------
__global__ void __cluster_dims__(8, 1, 1) __launch_bounds__(256, 1) lstm_scan(
    const float* __restrict__ gx, const float* __restrict__ w_hh,
    float* __restrict__ h_out)
{
    extern __shared__ float sm[];
    float* Wt   = sm;                  // [256][128]
    float* h4   = sm + 32768;          // [2][256][4]
    float* part = sm + 32768 + 2048;   // [8][4][128]

    cg::cluster_group cluster = cg::this_cluster();
    const unsigned rank = cluster.block_rank();
    const int tid = threadIdx.x;
    const int w = tid >> 5, l = tid & 31;
    const int bb = tid >> 5;
    const int ul = tid & 31;
    const int gbase = rank * 32 + ul;

    for (int idx = tid; idx < 128 * 256; idx += 256) {
        int j = idx & 127, k = idx >> 7;
        int gate = j >> 5, u = j & 31;
        int row = gate * Hq + rank * 32 + u;
        Wt[k * 128 + j] = w_hh[(size_t)row * Hq + k];
    }
    for (int idx = tid; idx < 2048; idx += 256) h4[idx] = 0.f;

    float* peers[8];
#pragma unroll
    for (int r = 0; r < 8; r++) peers[r] = cluster.map_shared_rank(h4, r);

    cluster.sync();

    float c0 = 0.f;
    const float* wt0 = Wt + 4 * l;

    for (int t = 0; t < Tq; t++) {
        const int p = t & 1;
        const float* hb = h4 + (p << 10);

        float pre_i = 0.f, pre_f = 0.f, pre_g = 0.f, pre_o = 0.f;
        if (tid < 128) {
            size_t base = ((size_t)bb * Tq + t) * G4q + gbase;
            pre_i = gx[base];
            pre_f = gx[base + Hq];
            pre_g = gx[base + 2 * Hq];
            pre_o = gx[base + 3 * Hq];
        }

        float a00=0,a01=0,a02=0,a03=0,a10=0,a11=0,a12=0,a13=0;
        float a20=0,a21=0,a22=0,a23=0,a30=0,a31=0,a32=0,a33=0;
#pragma unroll 4
        for (int kk = 0; kk < 32; kk++) {
            int k = (w << 5) + kk;
            float4 hv = *(const float4*)(hb + (k << 2));
            float4 wv = *(const float4*)(wt0 + (k << 7));
            a00 = fmaf(wv.x, hv.x, a00); a01 = fmaf(wv.y, hv.x, a01);
            a02 = fmaf(wv.z, hv.x, a02); a03 = fmaf(wv.w, hv.x, a03);
            a10 = fmaf(wv.x, hv.y, a10); a11 = fmaf(wv.y, hv.y, a11);
            a12 = fmaf(wv.z, hv.y, a12); a13 = fmaf(wv.w, hv.y, a13);
            a20 = fmaf(wv.x, hv.z, a20); a21 = fmaf(wv.y, hv.z, a21);
            a22 = fmaf(wv.z, hv.z, a22); a23 = fmaf(wv.w, hv.z, a23);
            a30 = fmaf(wv.x, hv.w, a30); a31 = fmaf(wv.y, hv.w, a31);
            a32 = fmaf(wv.z, hv.w, a32); a33 = fmaf(wv.w, hv.w, a33);
        }
        {
            float* pb = part + (w << 9) + (l << 2);
            *(float4*)(pb)       = make_float4(a00, a01, a02, a03);
            *(float4*)(pb + 128) = make_float4(a10, a11, a12, a13);
            *(float4*)(pb + 256) = make_float4(a20, a21, a22, a23);
            *(float4*)(pb + 384) = make_float4(a30, a31, a32, a33);
        }
        __syncthreads();

        if (tid < 128) {
            float gi = pre_i, gf = pre_f, gg = pre_g, go = pre_o;
#pragma unroll
            for (int ww = 0; ww < 8; ww++) {
                const float* pp = part + (ww << 9) + (bb << 7);
                gi += pp[ul];
                gf += pp[32 + ul];
                gg += pp[64 + ul];
                go += pp[96 + ul];
            }
            c0 = sigp(gf) * c0 + sigp(gi) * tanhf(gg);
            float hnew = sigp(go) * tanhf(c0);
            h_out[((size_t)bb * Tq + t) * Hq + gbase] = hnew;
            int off = ((p ^ 1) << 10) + (gbase << 2) + bb;
            h4[off] = hnew;
#pragma unroll
            for (int r = 0; r < 8; r++) {
                if (r != (int)rank) peers[r][off] = hnew;
            }
        }
        cluster.sync();
    }
}

// ---------------- attention (last query row only) ----------------
__global__ __launch_bounds__(256) void attn_last(
    const float* __restrict__ qkv_w, const float* __restrict__ qkv_b)
{
    __shared__ float q[64];
    __shared__ float sc[Tq];
    __shared__ float red[256];
    __shared__ float vp[256];
    const int bh = blockIdx.x;
    const int b = bh >> 3, h = bh & 7;
    const int tid = threadIdx.x;

    if (tid < 64) {
        int row = h * 64 + tid;
        const float* wr = qkv_w + (size_t)row * Dq;
        const float* ml = g_h2 + ((size_t)b * Tq + (Tq - 1)) * Hq;
        const float* mc = g_cv + ((size_t)b * Tq + (Tq - 1)) * Hq;
        float acc = qkv_b[row];
        for (int k = 0; k < 256; k++) acc = fmaf(ml[k], wr[k], acc);
        for (int k = 0; k < 256; k++) acc = fmaf(mc[k], wr[256 + k], acc);
        q[tid] = acc * 0.125f;
    }
    __syncthreads();

    float lmax = -1e30f;
    for (int t = tid; t < Tq; t += 256) {
        const float4* kp = (const float4*)(g_kv + ((size_t)b * Tq + t) * G4q + h * 64);
        float s = 0.f;
#pragma unroll
        for (int d4 = 0; d4 < 16; d4++) {
            float4 kk = kp[d4];
            float4 qq = ((const float4*)q)[d4];
            s += kk.x * qq.x + kk.y * qq.y + kk.z * qq.z + kk.w * qq.w;
        }
        sc[t] = s;
        lmax = fmaxf(lmax, s);
    }
    red[tid] = lmax; __syncthreads();
    for (int s2 = 128; s2 > 0; s2 >>= 1) {
        if (tid < s2) red[tid] = fmaxf(red[tid], red[tid + s2]);
        __syncthreads();
    }
    float m = red[0];
    __syncthreads();

    float lsum = 0.f;
    for (int t = tid; t < Tq; t += 256) {
        float pe = __expf(sc[t] - m);
        sc[t] = pe;
        lsum += pe;
    }
    red[tid] = lsum; __syncthreads();
    for (int s2 = 128; s2 > 0; s2 >>= 1) {
        if (tid < s2) red[tid] += red[tid + s2];
        __syncthreads();
    }
    float denom = red[0];
    __syncthreads();

    const int d = tid & 63, g = tid >> 6;
    float acc = 0.f;
    for (int t = g * 512; t < (g + 1) * 512; t++)
        acc = fmaf(sc[t], g_kv[((size_t)b * Tq + t) * G4q + 512 + h * 64 + d], acc);
    vp[tid] = acc; __syncthreads();
    if (tid < 64) {
        float o = (vp[tid] + vp[64 + tid] + vp[128 + tid] + vp[192 + tid]) / denom;
        g_at[b * Dq + h * 64 + tid] = o;
    }
}

// ---------------- head ----------------
__global__ __launch_bounds__(512) void head_kernel(
    const float* __restrict__ pw, const float* __restrict__ pb,
    const float* __restrict__ lng, const float* __restrict__ lnb,
    const float* __restrict__ f1w, const float* __restrict__ f1b,
    const float* __restrict__ f2w, const float* __restrict__ f2b,
    float* __restrict__ out)
{
    __shared__ float a[Dq], zn[Dq], z2[Hq], red[512];
    const int b = blockIdx.x, tid = threadIdx.x;
    a[tid] = g_at[b * Dq + tid];
    __syncthreads();

    float acc = pb[tid];
    const float* wr = pw + (size_t)tid * Dq;
    for (int k = 0; k < Dq; k++) acc = fmaf(a[k], wr[k], acc);
    float mrg = (tid < 256) ? g_h2[((size_t)b * Tq + Tq - 1) * Hq + tid]
                            : g_cv[((size_t)b * Tq + Tq - 1) * Hq + tid - 256];
    float z = acc + mrg;

    red[tid] = z; __syncthreads();
    for (int s = 256; s > 0; s >>= 1) {
        if (tid < s) red[tid] += red[tid + s];
        __syncthreads();
    }
    float mu = red[0] / 512.f;
    __syncthreads();
    float dv = z - mu;
    red[tid] = dv * dv; __syncthreads();
    for (int s = 256; s > 0; s >>= 1) {
        if (tid < s) red[tid] += red[tid + s];
        __syncthreads();
    }
    float var = red[0] / 512.f;
    __syncthreads();

    zn[tid] = dv * rsqrtf(var + EPSq) * lng[tid] + lnb[tid];
    __syncthreads();

    if (tid < 256) {
        float a2 = f1b[tid];
        const float* w1 = f1w + (size_t)tid * Dq;
        for (int k = 0; k < Dq; k++) a2 = fmaf(zn[k], w1[k], a2);
        z2[tid] = a2 / (1.f + expf(-a2));
    }
    __syncthreads();

    if (tid < 3) {
        float lg = f2b[tid];
        const float* w2 = f2w + tid * 256;
        for (int j = 0; j < 256; j++) lg = fmaf(z2[j], w2[j], lg);
        if (tid == 0)      out[b]     = tanhf(lg);
        else if (tid == 1) out[4 + b] = (lg > 20.f) ? lg : log1pf(expf(lg));
        else               out[8 + b] = 1.f / (1.f + expf(-lg));
    }
}

// ---------------- launch ----------------
extern "C" void kernel_launch(void* const* d_in, const int* in_sizes, int n_in,
                              void* d_out, int out_size) {
    const float* x     = (const float*)d_in[0];
    const float* wih0  = (const float*)d_in[1];
    const float* whh0  = (const float*)d_in[2];
    const float* bih0  = (const float*)d_in[3];
    const float* bhh0  = (const float*)d_in[4];
    const float* wih1  = (const float*)d_in[5];
    const float* whh1  = (const float*)d_in[6];
    const float* bih1  = (const float*)d_in[7];
    const float* bhh1  = (const float*)d_in[8];
    const float* cw    = (const float*)d_in[9];
    const float* cb    = (const float*)d_in[10];
    const float* bng   = (const float*)d_in[11];
    const float* bnb   = (const float*)d_in[12];
    const float* bnm   = (const float*)d_in[13];
    const float* bnv   = (const float*)d_in[14];
    const float* qkvw  = (const float*)d_in[15];
    const float* qkvb  = (const float*)d_in[16];
    const float* pw    = (const float*)d_in[17];
    const float* pbv   = (const float*)d_in[18];
    const float* lng   = (const float*)d_in[19];
    const float* lnb   = (const float*)d_in[20];
    const float* f1w   = (const float*)d_in[21];
    const float* f1b   = (const float*)d_in[22];
    const float* f2w   = (const float*)d_in[23];
    const float* f2b   = (const float*)d_in[24];
    float* out = (float*)d_out;

    float *gx0, *gx1, *h1, *h2, *cv, *kv;
    cudaGetSymbolAddress((void**)&gx0, g_gx0);
    cudaGetSymbolAddress((void**)&gx1, g_gx1);
    cudaGetSymbolAddress((void**)&h1,  g_h1);
    cudaGetSymbolAddress((void**)&h2,  g_h2);
    cudaGetSymbolAddress((void**)&cv,  g_cv);
    cudaGetSymbolAddress((void**)&kv,  g_kv);

    const int scan_smem = (32768 + 2048 + 4096) * 4;
    const int conv_smem = (36 * 64 + 64 * 321) * 4;
    cudaFuncSetAttribute(lstm_scan, cudaFuncAttributeMaxDynamicSharedMemorySize, scan_smem);
    cudaFuncSetAttribute(conv_bn_silu, cudaFuncAttributeMaxDynamicSharedMemorySize, conv_smem);

    // gx0 = x @ w_ih0^T + b_ih0 + b_hh0
    gemm64<<<dim3(128, 16), 256>>>(x, nullptr, 64, 64, wih0, bih0, bhh0, gx0, G4q);
    // conv branch (independent of LSTM)
    conv_bn_silu<<<dim3(64, 4, 4), 256, conv_smem>>>(x, cw, cb, bng, bnb, bnm, bnv);
    // layer-0 scan
    lstm_scan<<<8, 256, scan_smem>>>(gx0, whh0, h1);
    // gx1 = h1 @ w_ih1^T + b_ih1 + b_hh1
    gemm64<<<dim3(128, 16), 256>>>(h1, nullptr, 256, 256, wih1, bih1, bhh1, gx1, G4q);
    // layer-1 scan
    lstm_scan<<<8, 256, scan_smem>>>(gx1, whh1, h2);
    // kv = merged @ qkv_w[512:1536]^T + qkv_b[512:1536]
    gemm64<<<dim3(128, 16), 256>>>(h2, cv, 256, 512, qkvw + 512 * 512, qkvb + 512,
                                   nullptr, kv, G4q);
    // attention (last row only)
    attn_last<<<32, 256>>>(qkvw, qkvb);
    // head
    head_kernel<<<4, 512>>>(pw, pbv, lng, lnb, f1w, f1b, f2w, f2b, out);
}

// round 4
// speedup vs baseline: 1.1543x; 1.1543x over previous
#include <cuda_runtime.h>
#include <cooperative_groups.h>
#include <math.h>

namespace cg = cooperative_groups;

#define Bq   4
#define Tq   2048
#define INq  64
#define Hq   256
#define Dq   512
#define G4q  1024
#define EPSq 1e-5f

// ---------------- static scratch ----------------
__device__ float g_gx0[Bq * Tq * G4q];
__device__ float g_gx1[Bq * Tq * G4q];
__device__ float g_h1 [Bq * Tq * Hq];
__device__ float g_h2 [Bq * Tq * Hq];
__device__ float g_cv [Bq * Tq * Hq];
__device__ float g_kv [Bq * Tq * G4q];
__device__ float g_at [Bq * Dq];

__device__ __forceinline__ float sigp(float x) { return 1.f / (1.f + expf(-x)); }
__device__ __forceinline__ float sigfast(float x) {
    return __fdividef(1.f, 1.f + __expf(-x));
}
__device__ __forceinline__ float tanhfast(float x) {
    return 1.f - __fdividef(2.f, __expf(2.f * x) + 1.f);
}

// ---------------- GEMM: out[m,n] = sum_k A[m,k]*W[n,k] + b1[n] (+ b2[n]) ---------
__global__ __launch_bounds__(256) void gemm64(
    const float* __restrict__ A1, const float* __restrict__ A2,
    int Ksplit, int K,
    const float* __restrict__ W, const float* __restrict__ b1,
    const float* __restrict__ b2, float* __restrict__ out, int N)
{
    __shared__ float As[16][64];
    __shared__ float Bs[16][64];
    const int m0 = blockIdx.x * 64, n0 = blockIdx.y * 64;
    const int tid = threadIdx.x;
    const int tx = tid & 15, ty = tid >> 4;
    const int lm = tid >> 2;
    const int lk4 = (tid & 3) * 4;
    const int K2 = K - Ksplit;

    float acc[4][4];
#pragma unroll
    for (int i = 0; i < 4; i++)
#pragma unroll
        for (int j = 0; j < 4; j++) acc[i][j] = 0.f;

    for (int k0 = 0; k0 < K; k0 += 16) {
        {
            int m = m0 + lm;
            int kg = k0 + lk4;
            float4 v;
            if (kg < Ksplit) v = *(const float4*)(A1 + (size_t)m * Ksplit + kg);
            else             v = *(const float4*)(A2 + (size_t)m * K2 + (kg - Ksplit));
            As[lk4 + 0][lm] = v.x; As[lk4 + 1][lm] = v.y;
            As[lk4 + 2][lm] = v.z; As[lk4 + 3][lm] = v.w;
            int n = n0 + lm;
            float4 wv = *(const float4*)(W + (size_t)n * K + k0 + lk4);
            Bs[lk4 + 0][lm] = wv.x; Bs[lk4 + 1][lm] = wv.y;
            Bs[lk4 + 2][lm] = wv.z; Bs[lk4 + 3][lm] = wv.w;
        }
        __syncthreads();
#pragma unroll
        for (int kk = 0; kk < 16; kk++) {
            float4 a = *(const float4*)&As[kk][ty * 4];
            float4 b = *(const float4*)&Bs[kk][tx * 4];
            acc[0][0] = fmaf(a.x, b.x, acc[0][0]); acc[0][1] = fmaf(a.x, b.y, acc[0][1]);
            acc[0][2] = fmaf(a.x, b.z, acc[0][2]); acc[0][3] = fmaf(a.x, b.w, acc[0][3]);
            acc[1][0] = fmaf(a.y, b.x, acc[1][0]); acc[1][1] = fmaf(a.y, b.y, acc[1][1]);
            acc[1][2] = fmaf(a.y, b.z, acc[1][2]); acc[1][3] = fmaf(a.y, b.w, acc[1][3]);
            acc[2][0] = fmaf(a.z, b.x, acc[2][0]); acc[2][1] = fmaf(a.z, b.y, acc[2][1]);
            acc[2][2] = fmaf(a.z, b.z, acc[2][2]); acc[2][3] = fmaf(a.z, b.w, acc[2][3]);
            acc[3][0] = fmaf(a.w, b.x, acc[3][0]); acc[3][1] = fmaf(a.w, b.y, acc[3][1]);
            acc[3][2] = fmaf(a.w, b.z, acc[3][2]); acc[3][3] = fmaf(a.w, b.w, acc[3][3]);
        }
        __syncthreads();
    }

    float bias[4];
#pragma unroll
    for (int j = 0; j < 4; j++) {
        int n = n0 + tx * 4 + j;
        bias[j] = b1[n] + (b2 ? b2[n] : 0.f);
    }
#pragma unroll
    for (int i = 0; i < 4; i++) {
        int m = m0 + ty * 4 + i;
        float4 r = make_float4(acc[i][0] + bias[0], acc[i][1] + bias[1],
                               acc[i][2] + bias[2], acc[i][3] + bias[3]);
        *(float4*)(out + (size_t)m * N + n0 + tx * 4) = r;
    }
}

// ---------------- conv1d(K=5,same) + BN + SiLU ----------------
__global__ __launch_bounds__(256, 1) void conv_bn_silu(
    const float* __restrict__ x, const float* __restrict__ cw,
    const float* __restrict__ cb, const float* __restrict__ bg,
    const float* __restrict__ bnb, const float* __restrict__ bmean,
    const float* __restrict__ bvar)
{
    extern __shared__ float sm[];
    float* xs = sm;              // [36][64]
    float* ws = sm + 36 * 64;    // [64][321]
    const int b = blockIdx.z;
    const int t0 = blockIdx.x * 32;
    const int ocb = blockIdx.y * 64;
    const int tid = threadIdx.x;

    for (int idx = tid; idx < 36 * 64; idx += 256) {
        int tr = idx >> 6, i = idx & 63;
        int tg = t0 + tr - 2;
        xs[idx] = (tg >= 0 && tg < Tq) ? x[((size_t)b * Tq + tg) * INq + i] : 0.f;
    }
    for (int idx = tid; idx < 64 * 320; idx += 256) {
        int o = idx / 320, ik = idx % 320;
        ws[o * 321 + ik] = cw[(size_t)(ocb + o) * 320 + ik];
    }
    __syncthreads();

    const int o = tid & 63, gq = tid >> 6;
    const int tb = gq * 8;
    float acc[8];
#pragma unroll
    for (int t = 0; t < 8; t++) acc[t] = 0.f;

    for (int i = 0; i < 64; i++) {
        float xv[12];
#pragma unroll
        for (int j = 0; j < 12; j++) xv[j] = xs[(tb + j) * 64 + i];
#pragma unroll
        for (int k = 0; k < 5; k++) {
            float wv = ws[o * 321 + i * 5 + k];
#pragma unroll
            for (int t = 0; t < 8; t++) acc[t] = fmaf(xv[t + k], wv, acc[t]);
        }
    }
    const int oc = ocb + o;
    float scl = rsqrtf(bvar[oc] + EPSq) * bg[oc];
    float sh = bnb[oc] - bmean[oc] * scl;
    float cbv = cb[oc];
#pragma unroll
    for (int t = 0; t < 8; t++) {
        float y = (acc[t] + cbv) * scl + sh;
        g_cv[((size_t)b * Tq + t0 + tb + t) * Hq + oc] = y / (1.f + __expf(-y));
    }
}

// ---------------- mbarrier helpers ----------------
#define MBAR_WAIT_ACQ_CLUSTER(addr, par) do {                                    \
    unsigned _done;                                                              \
    asm volatile("{\n\t.reg .pred P;\n\t"                                        \
        "mbarrier.try_wait.parity.acquire.cluster.shared::cta.b64 P, [%1], %2;\n\t" \
        "selp.b32 %0, 1, 0, P;\n\t}"                                             \
        : "=r"(_done) : "r"(addr), "r"(par) : "memory");                         \
    while (!_done) {                                                             \
        asm volatile("{\n\t.reg .pred P;\n\t"                                    \
            "mbarrier.try_wait.parity.acquire.cluster.shared::cta.b64 P, [%1], %2, 0x989680;\n\t" \
            "selp.b32 %0, 1, 0, P;\n\t}"                                         \
            : "=r"(_done) : "r"(addr), "r"(par) : "memory");                     \
    }                                                                            \
} while (0)

#define MBAR_ARRIVE_REL_CLUSTER(addr, r) \
    asm volatile("{\n\t.reg .b32 ra;\n\t"                                        \
        "mapa.shared::cluster.u32 ra, %0, %1;\n\t"                               \
        "mbarrier.arrive.release.cluster.shared::cluster.b64 _, [ra];\n\t}"      \
        :: "r"(addr), "r"(r) : "memory")

// ---------------- LSTM scan: 4 clusters x 8 CTAs, one batch per cluster --------
// gx holds x@w_ih^T + b_ih + b_hh. Each CTA owns 32 hidden units (4x32 gate rows).
__global__ void __cluster_dims__(8, 1, 1) __launch_bounds__(256, 1) lstm_scan(
    const float* __restrict__ gx, const float* __restrict__ w_hh,
    float* __restrict__ h_out)
{
    extern __shared__ float sm[];
    float* Wt   = sm;                     // [256][128]  Wt[k*128 + j]
    float* h2   = sm + 32768;             // [2][256] double-buffered h
    float* part = sm + 32768 + 512;       // [8][128] per-warp partials
    unsigned long long* mbar = (unsigned long long*)(sm + 32768 + 512 + 1024);

    cg::cluster_group cluster = cg::this_cluster();
    const int rank  = (int)cluster.block_rank();
    const int batch = blockIdx.x >> 3;
    const int tid = threadIdx.x;
    const int w = tid >> 5, l = tid & 31;

    // Wt[k*128 + j] = w_hh[(gate*256 + rank*32 + u) * 256 + k],  j = gate*32 + u
    for (int idx = tid; idx < 128 * 256; idx += 256) {
        int j = idx & 127, k = idx >> 7;
        int row = (j >> 5) * 256 + rank * 32 + (j & 31);
        Wt[idx] = w_hh[(size_t)row * 256 + k];
    }
    if (tid < 512) h2[tid] = 0.f;

    uint32_t mbar_addr;
    asm("{ .reg .u64 t; cvta.to.shared.u64 t, %1; cvt.u32.u64 %0, t; }"
        : "=r"(mbar_addr) : "l"((void*)mbar));
    if (tid == 0) {
        asm volatile("mbarrier.init.shared.b64 [%0], %1;"
                     :: "r"(mbar_addr), "r"(256) : "memory");
    }
    float* peer_h[8];
#pragma unroll
    for (int r = 0; r < 8; r++) peer_h[r] = cluster.map_shared_rank(h2, r);

    cluster.sync();

    const int u = l;
    const int gbase = rank * 32 + u;
    float c0 = 0.f;
    const float* wt0 = Wt + 4 * l;

    // prefetch gx(0)
    float cur0 = 0.f, cur1 = 0.f, cur2 = 0.f, cur3 = 0.f;
    if (w == 0) {
        size_t base = (size_t)batch * Tq * G4q + gbase;
        cur0 = gx[base];
        cur1 = gx[base + 256];
        cur2 = gx[base + 512];
        cur3 = gx[base + 768];
    }

    for (int t = 0; t < Tq; t++) {
        // prefetch gx(t+1) (independent of the barrier — issue before waiting)
        float nxt0 = 0.f, nxt1 = 0.f, nxt2 = 0.f, nxt3 = 0.f;
        if (w == 0 && t + 1 < Tq) {
            size_t base = ((size_t)batch * Tq + t + 1) * G4q + gbase;
            nxt0 = gx[base];
            nxt1 = gx[base + 256];
            nxt2 = gx[base + 512];
            nxt3 = gx[base + 768];
        }

        if (t > 0) {
            unsigned par = (unsigned)((t - 1) & 1);
            MBAR_WAIT_ACQ_CLUSTER(mbar_addr, par);
        }
        const int p = t & 1;
        const float* hb = h2 + (p << 8);

        // matvec: warp w does k in [32w, 32w+32); lane l owns rows 4l..4l+3
        float a0 = 0.f, a1 = 0.f, a2 = 0.f, a3 = 0.f;
#pragma unroll
        for (int kk = 0; kk < 32; kk += 4) {
            int k = (w << 5) + kk;
            float4 hv = *(const float4*)(hb + k);
            float4 w0v = *(const float4*)(wt0 + (size_t)(k + 0) * 128);
            float4 w1v = *(const float4*)(wt0 + (size_t)(k + 1) * 128);
            float4 w2v = *(const float4*)(wt0 + (size_t)(k + 2) * 128);
            float4 w3v = *(const float4*)(wt0 + (size_t)(k + 3) * 128);
            a0 = fmaf(w0v.x, hv.x, a0); a1 = fmaf(w0v.y, hv.x, a1);
            a2 = fmaf(w0v.z, hv.x, a2); a3 = fmaf(w0v.w, hv.x, a3);
            a0 = fmaf(w1v.x, hv.y, a0); a1 = fmaf(w1v.y, hv.y, a1);
            a2 = fmaf(w1v.z, hv.y, a2); a3 = fmaf(w1v.w, hv.y, a3);
            a0 = fmaf(w2v.x, hv.z, a0); a1 = fmaf(w2v.y, hv.z, a1);
            a2 = fmaf(w2v.z, hv.z, a2); a3 = fmaf(w2v.w, hv.z, a3);
            a0 = fmaf(w3v.x, hv.w, a0); a1 = fmaf(w3v.y, hv.w, a1);
            a2 = fmaf(w3v.z, hv.w, a2); a3 = fmaf(w3v.w, hv.w, a3);
        }
        *(float4*)(part + (w << 7) + (l << 2)) = make_float4(a0, a1, a2, a3);
        __syncthreads();

        if (w == 0) {
            float s0 = cur0, s1 = cur1, s2 = cur2, s3 = cur3;
#pragma unroll
            for (int ww = 0; ww < 8; ww++) {
                const float* pp = part + (ww << 7);
                s0 += pp[u];
                s1 += pp[32 + u];
                s2 += pp[64 + u];
                s3 += pp[96 + u];
            }
            float gi = sigfast(s0), gf = sigfast(s1);
            float gc = tanhfast(s2), go = sigfast(s3);
            c0 = gf * c0 + gi * gc;
            float hnew = go * tanhfast(c0);
            h_out[((size_t)batch * Tq + t) * Hq + gbase] = hnew;

            if (t + 1 < Tq) {
                int off = ((p ^ 1) << 8) + gbase;
#pragma unroll
                for (int r = 0; r < 8; r++) peer_h[r][off] = hnew;
#pragma unroll
                for (int r = 0; r < 8; r++) MBAR_ARRIVE_REL_CLUSTER(mbar_addr, r);
            }
            cur0 = nxt0; cur1 = nxt1; cur2 = nxt2; cur3 = nxt3;
        }
    }
    cluster.sync();
}

// ---------------- attention (last query row only) ----------------
__global__ __launch_bounds__(256) void attn_last(
    const float* __restrict__ qkv_w, const float* __restrict__ qkv_b)
{
    __shared__ float q[64];
    __shared__ float sc[Tq];
    __shared__ float red[256];
    __shared__ float vp[256];
    const int bh = blockIdx.x;
    const int b = bh >> 3, h = bh & 7;
    const int tid = threadIdx.x;

    if (tid < 64) {
        int row = h * 64 + tid;
        const float* wr = qkv_w + (size_t)row * Dq;
        const float* ml = g_h2 + ((size_t)b * Tq + (Tq - 1)) * Hq;
        const float* mc = g_cv + ((size_t)b * Tq + (Tq - 1)) * Hq;
        float acc = qkv_b[row];
        for (int k = 0; k < 256; k++) acc = fmaf(ml[k], wr[k], acc);
        for (int k = 0; k < 256; k++) acc = fmaf(mc[k], wr[256 + k], acc);
        q[tid] = acc * 0.125f;
    }
    __syncthreads();

    float lmax = -1e30f;
    for (int t = tid; t < Tq; t += 256) {
        const float4* kp = (const float4*)(g_kv + ((size_t)b * Tq + t) * G4q + h * 64);
        float s = 0.f;
#pragma unroll
        for (int d4 = 0; d4 < 16; d4++) {
            float4 kk = kp[d4];
            float4 qq = ((const float4*)q)[d4];
            s += kk.x * qq.x + kk.y * qq.y + kk.z * qq.z + kk.w * qq.w;
        }
        sc[t] = s;
        lmax = fmaxf(lmax, s);
    }
    red[tid] = lmax; __syncthreads();
    for (int s2 = 128; s2 > 0; s2 >>= 1) {
        if (tid < s2) red[tid] = fmaxf(red[tid], red[tid + s2]);
        __syncthreads();
    }
    float m = red[0];
    __syncthreads();

    float lsum = 0.f;
    for (int t = tid; t < Tq; t += 256) {
        float pe = __expf(sc[t] - m);
        sc[t] = pe;
        lsum += pe;
    }
    red[tid] = lsum; __syncthreads();
    for (int s2 = 128; s2 > 0; s2 >>= 1) {
        if (tid < s2) red[tid] += red[tid + s2];
        __syncthreads();
    }
    float denom = red[0];
    __syncthreads();

    const int d = tid & 63, g = tid >> 6;
    float acc = 0.f;
    for (int t = g * 512; t < (g + 1) * 512; t++)
        acc = fmaf(sc[t], g_kv[((size_t)b * Tq + t) * G4q + 512 + h * 64 + d], acc);
    vp[tid] = acc; __syncthreads();
    if (tid < 64) {
        float o = (vp[tid] + vp[64 + tid] + vp[128 + tid] + vp[192 + tid]) / denom;
        g_at[b * Dq + h * 64 + tid] = o;
    }
}

// ---------------- head ----------------
__global__ __launch_bounds__(512) void head_kernel(
    const float* __restrict__ pw, const float* __restrict__ pb,
    const float* __restrict__ lng, const float* __restrict__ lnb,
    const float* __restrict__ f1w, const float* __restrict__ f1b,
    const float* __restrict__ f2w, const float* __restrict__ f2b,
    float* __restrict__ out)
{
    __shared__ float a[Dq], zn[Dq], z2[Hq], red[512];
    const int b = blockIdx.x, tid = threadIdx.x;
    a[tid] = g_at[b * Dq + tid];
    __syncthreads();

    float acc = pb[tid];
    const float* wr = pw + (size_t)tid * Dq;
    for (int k = 0; k < Dq; k++) acc = fmaf(a[k], wr[k], acc);
    float mrg = (tid < 256) ? g_h2[((size_t)b * Tq + Tq - 1) * Hq + tid]
                            : g_cv[((size_t)b * Tq + Tq - 1) * Hq + tid - 256];
    float z = acc + mrg;

    red[tid] = z; __syncthreads();
    for (int s = 256; s > 0; s >>= 1) {
        if (tid < s) red[tid] += red[tid + s];
        __syncthreads();
    }
    float mu = red[0] / 512.f;
    __syncthreads();
    float dv = z - mu;
    red[tid] = dv * dv; __syncthreads();
    for (int s = 256; s > 0; s >>= 1) {
        if (tid < s) red[tid] += red[tid + s];
        __syncthreads();
    }
    float var = red[0] / 512.f;
    __syncthreads();

    zn[tid] = dv * rsqrtf(var + EPSq) * lng[tid] + lnb[tid];
    __syncthreads();

    if (tid < 256) {
        float a2 = f1b[tid];
        const float* w1 = f1w + (size_t)tid * Dq;
        for (int k = 0; k < Dq; k++) a2 = fmaf(zn[k], w1[k], a2);
        z2[tid] = a2 / (1.f + expf(-a2));
    }
    __syncthreads();

    if (tid < 3) {
        float lg = f2b[tid];
        const float* w2 = f2w + tid * 256;
        for (int j = 0; j < 256; j++) lg = fmaf(z2[j], w2[j], lg);
        if (tid == 0)      out[b]     = tanhf(lg);
        else if (tid == 1) out[4 + b] = (lg > 20.f) ? lg : log1pf(expf(lg));
        else               out[8 + b] = 1.f / (1.f + expf(-lg));
    }
}

// ---------------- launch ----------------
extern "C" void kernel_launch(void* const* d_in, const int* in_sizes, int n_in,
                              void* d_out, int out_size) {
    const float* x     = (const float*)d_in[0];
    const float* wih0  = (const float*)d_in[1];
    const float* whh0  = (const float*)d_in[2];
    const float* bih0  = (const float*)d_in[3];
    const float* bhh0  = (const float*)d_in[4];
    const float* wih1  = (const float*)d_in[5];
    const float* whh1  = (const float*)d_in[6];
    const float* bih1  = (const float*)d_in[7];
    const float* bhh1  = (const float*)d_in[8];
    const float* cw    = (const float*)d_in[9];
    const float* cb    = (const float*)d_in[10];
    const float* bng   = (const float*)d_in[11];
    const float* bnb   = (const float*)d_in[12];
    const float* bnm   = (const float*)d_in[13];
    const float* bnv   = (const float*)d_in[14];
    const float* qkvw  = (const float*)d_in[15];
    const float* qkvb  = (const float*)d_in[16];
    const float* pw    = (const float*)d_in[17];
    const float* pbv   = (const float*)d_in[18];
    const float* lng   = (const float*)d_in[19];
    const float* lnb   = (const float*)d_in[20];
    const float* f1w   = (const float*)d_in[21];
    const float* f1b   = (const float*)d_in[22];
    const float* f2w   = (const float*)d_in[23];
    const float* f2b   = (const float*)d_in[24];
    float* out = (float*)d_out;

    float *gx0, *gx1, *h1, *h2, *cv, *kv;
    cudaGetSymbolAddress((void**)&gx0, g_gx0);
    cudaGetSymbolAddress((void**)&gx1, g_gx1);
    cudaGetSymbolAddress((void**)&h1,  g_h1);
    cudaGetSymbolAddress((void**)&h2,  g_h2);
    cudaGetSymbolAddress((void**)&cv,  g_cv);
    cudaGetSymbolAddress((void**)&kv,  g_kv);

    const int scan_smem = (32768 + 512 + 1024) * 4 + 16;   // Wt + h2 + part + mbar
    const int conv_smem = (36 * 64 + 64 * 321) * 4;
    cudaFuncSetAttribute(lstm_scan, cudaFuncAttributeMaxDynamicSharedMemorySize, scan_smem);
    cudaFuncSetAttribute(conv_bn_silu, cudaFuncAttributeMaxDynamicSharedMemorySize, conv_smem);

    // gx0 = x @ w_ih0^T + b_ih0 + b_hh0
    gemm64<<<dim3(128, 16), 256>>>(x, nullptr, 64, 64, wih0, bih0, bhh0, gx0, G4q);
    // conv branch (independent of LSTM)
    conv_bn_silu<<<dim3(64, 4, 4), 256, conv_smem>>>(x, cw, cb, bng, bnb, bnm, bnv);
    // layer-0 scan: 4 clusters (one per batch) x 8 CTAs
    lstm_scan<<<32, 256, scan_smem>>>(gx0, whh0, h1);
    // gx1 = h1 @ w_ih1^T + b_ih1 + b_hh1
    gemm64<<<dim3(128, 16), 256>>>(h1, nullptr, 256, 256, wih1, bih1, bhh1, gx1, G4q);
    // layer-1 scan
    lstm_scan<<<32, 256, scan_smem>>>(gx1, whh1, h2);
    // kv = merged @ qkv_w[512:1536]^T + qkv_b[512:1536]
    gemm64<<<dim3(128, 16), 256>>>(h2, cv, 256, 512, qkvw + 512 * 512, qkvb + 512,
                                   nullptr, kv, G4q);
    // attention (last row only)
    attn_last<<<32, 256>>>(qkvw, qkvb);
    // head
    head_kernel<<<4, 512>>>(pw, pbv, lng, lnb, f1w, f1b, f2w, f2b, out);
}

// round 5
// speedup vs baseline: 2.2341x; 1.9354x over previous
#include <cuda_runtime.h>
#include <cooperative_groups.h>
#include <math.h>

namespace cg = cooperative_groups;

#define Bq   4
#define Tq   2048
#define INq  64
#define Hq   256
#define Dq   512
#define G4q  1024
#define EPSq 1e-5f

// ---------------- static scratch ----------------
__device__ float g_gx0[Bq * Tq * G4q];
__device__ float g_gx1[Bq * Tq * G4q];
__device__ float g_h1 [Bq * Tq * Hq];
__device__ float g_h2 [Bq * Tq * Hq];
__device__ float g_cv [Bq * Tq * Hq];
__device__ float g_kv [Bq * Tq * G4q];
__device__ float g_at [Bq * Dq];

__device__ __forceinline__ float sigfast(float x) {
    return __fdividef(1.f, 1.f + __expf(-x));
}
__device__ __forceinline__ float tanhfast(float x) {
    return 1.f - __fdividef(2.f, __expf(2.f * x) + 1.f);
}

// ---------------- GEMM 128x64 tiles: out[m,n] = sum_k A[m,k]*W[n,k] + b1[n](+b2[n])
// A split at Ksplit between A1/A2 (concat along k). 256 threads, 8x4 per thread.
__global__ __launch_bounds__(256) void gemm128(
    const float* __restrict__ A1, const float* __restrict__ A2,
    int Ksplit, int K,
    const float* __restrict__ W, const float* __restrict__ b1,
    const float* __restrict__ b2, float* __restrict__ out, int N)
{
    __shared__ float As[16][128];
    __shared__ float Bs[16][64];
    const int m0 = blockIdx.x * 128, n0 = blockIdx.y * 64;
    const int tid = threadIdx.x;
    const int tx = tid & 15, ty = tid >> 4;
    const int lmA = tid & 127, khA = (tid >> 7) * 8;
    const int lnB = tid & 63,  kB  = (tid >> 6) * 4;
    const int K2 = K - Ksplit;

    float acc[8][4];
#pragma unroll
    for (int i = 0; i < 8; i++)
#pragma unroll
        for (int j = 0; j < 4; j++) acc[i][j] = 0.f;

    for (int k0 = 0; k0 < K; k0 += 16) {
        {
            int m = m0 + lmA;
#pragma unroll
            for (int half = 0; half < 2; half++) {
                int off = khA + half * 4;
                int kg = k0 + off;
                float4 v;
                if (kg < Ksplit) v = *(const float4*)(A1 + (size_t)m * Ksplit + kg);
                else             v = *(const float4*)(A2 + (size_t)m * K2 + (kg - Ksplit));
                As[off + 0][lmA] = v.x; As[off + 1][lmA] = v.y;
                As[off + 2][lmA] = v.z; As[off + 3][lmA] = v.w;
            }
            int n = n0 + lnB;
            float4 wv = *(const float4*)(W + (size_t)n * K + k0 + kB);
            Bs[kB + 0][lnB] = wv.x; Bs[kB + 1][lnB] = wv.y;
            Bs[kB + 2][lnB] = wv.z; Bs[kB + 3][lnB] = wv.w;
        }
        __syncthreads();
#pragma unroll
        for (int kk = 0; kk < 16; kk++) {
            float4 a0 = *(const float4*)&As[kk][ty * 8];
            float4 a1 = *(const float4*)&As[kk][ty * 8 + 4];
            float4 b  = *(const float4*)&Bs[kk][tx * 4];
            float av[8] = {a0.x, a0.y, a0.z, a0.w, a1.x, a1.y, a1.z, a1.w};
#pragma unroll
            for (int i = 0; i < 8; i++) {
                acc[i][0] = fmaf(av[i], b.x, acc[i][0]);
                acc[i][1] = fmaf(av[i], b.y, acc[i][1]);
                acc[i][2] = fmaf(av[i], b.z, acc[i][2]);
                acc[i][3] = fmaf(av[i], b.w, acc[i][3]);
            }
        }
        __syncthreads();
    }

    float bias[4];
#pragma unroll
    for (int j = 0; j < 4; j++) {
        int n = n0 + tx * 4 + j;
        bias[j] = b1[n] + (b2 ? b2[n] : 0.f);
    }
#pragma unroll
    for (int i = 0; i < 8; i++) {
        int m = m0 + ty * 8 + i;
        float4 r = make_float4(acc[i][0] + bias[0], acc[i][1] + bias[1],
                               acc[i][2] + bias[2], acc[i][3] + bias[3]);
        *(float4*)(out + (size_t)m * N + n0 + tx * 4) = r;
    }
}

// ---------------- conv1d(K=5,same) + BN + SiLU ----------------
__global__ __launch_bounds__(256, 1) void conv_bn_silu(
    const float* __restrict__ x, const float* __restrict__ cw,
    const float* __restrict__ cb, const float* __restrict__ bg,
    const float* __restrict__ bnb, const float* __restrict__ bmean,
    const float* __restrict__ bvar)
{
    extern __shared__ float sm[];
    float* xs = sm;              // [36][64]
    float* ws = sm + 36 * 64;    // [64][321]
    const int b = blockIdx.z;
    const int t0 = blockIdx.x * 32;
    const int ocb = blockIdx.y * 64;
    const int tid = threadIdx.x;

    for (int idx = tid; idx < 36 * 64; idx += 256) {
        int tr = idx >> 6, i = idx & 63;
        int tg = t0 + tr - 2;
        xs[idx] = (tg >= 0 && tg < Tq) ? x[((size_t)b * Tq + tg) * INq + i] : 0.f;
    }
    for (int idx = tid; idx < 64 * 320; idx += 256) {
        int o = idx / 320, ik = idx % 320;
        ws[o * 321 + ik] = cw[(size_t)(ocb + o) * 320 + ik];
    }
    __syncthreads();

    const int o = tid & 63, gq = tid >> 6;
    const int tb = gq * 8;
    float acc[8];
#pragma unroll
    for (int t = 0; t < 8; t++) acc[t] = 0.f;

    for (int i = 0; i < 64; i++) {
        float xv[12];
#pragma unroll
        for (int j = 0; j < 12; j++) xv[j] = xs[(tb + j) * 64 + i];
#pragma unroll
        for (int k = 0; k < 5; k++) {
            float wv = ws[o * 321 + i * 5 + k];
#pragma unroll
            for (int t = 0; t < 8; t++) acc[t] = fmaf(xv[t + k], wv, acc[t]);
        }
    }
    const int oc = ocb + o;
    float scl = rsqrtf(bvar[oc] + EPSq) * bg[oc];
    float sh = bnb[oc] - bmean[oc] * scl;
    float cbv = cb[oc];
#pragma unroll
    for (int t = 0; t < 8; t++) {
        float y = (acc[t] + cbv) * scl + sh;
        g_cv[((size_t)b * Tq + t0 + tb + t) * Hq + oc] = y / (1.f + __expf(-y));
    }
}

// ---------------- mbarrier helpers ----------------
#define MBAR_WAIT_ACQ_CLUSTER(addr, par) do {                                    \
    unsigned _done;                                                              \
    asm volatile("{\n\t.reg .pred P;\n\t"                                        \
        "mbarrier.try_wait.parity.acquire.cluster.shared::cta.b64 P, [%1], %2;\n\t" \
        "selp.b32 %0, 1, 0, P;\n\t}"                                             \
        : "=r"(_done) : "r"(addr), "r"(par) : "memory");                         \
    while (!_done) {                                                             \
        asm volatile("{\n\t.reg .pred P;\n\t"                                    \
            "mbarrier.try_wait.parity.acquire.cluster.shared::cta.b64 P, [%1], %2, 0x989680;\n\t" \
            "selp.b32 %0, 1, 0, P;\n\t}"                                         \
            : "=r"(_done) : "r"(addr), "r"(par) : "memory");                     \
    }                                                                            \
} while (0)

#define MBAR_ARRIVE_REL_CLUSTER(addr, r) \
    asm volatile("{\n\t.reg .b32 ra;\n\t"                                        \
        "mapa.shared::cluster.u32 ra, %0, %1;\n\t"                               \
        "mbarrier.arrive.release.cluster.shared::cluster.b64 _, [ra];\n\t}"      \
        :: "r"(addr), "r"(r) : "memory")

// ---------------- LSTM scan: 4 clusters x 8 CTAs, one batch per cluster --------
// Register-resident weights; warp-local gate computation; 1 DSMEM store +
// 1 arrive per lane per step; no __syncthreads in the time loop.
// Lane map: unit v=l&3 (warp owns units 4w..4w+3), gate g=(l>>2)&3, khalf=l>>4,
// broadcast peer = l>>2.
__global__ void __cluster_dims__(8, 1, 1) __launch_bounds__(256, 1) lstm_scan(
    const float* __restrict__ gx, const float* __restrict__ w_hh,
    float* __restrict__ h_out)
{
    __shared__ float h2s[2][256];
    __shared__ alignas(8) unsigned long long mbar_storage;

    cg::cluster_group cluster = cg::this_cluster();
    const int rank  = (int)cluster.block_rank();
    const int batch = blockIdx.x >> 3;
    const int tid = threadIdx.x;
    const int w = tid >> 5, l = tid & 31;
    const int v  = l & 3;
    const int g  = (l >> 2) & 3;
    const int kh = l >> 4;
    const int peer = l >> 2;
    const int gunit = rank * 32 + w * 4 + v;     // global hidden unit 0..255
    const int row = g * Hq + gunit;              // gate row 0..1023

    // load this thread's 128 weights into registers
    float wreg[128];
    {
        const float* wp = w_hh + (size_t)row * Hq + (kh << 7);
#pragma unroll
        for (int i = 0; i < 32; i++) {
            float4 wv = *(const float4*)(wp + 4 * i);
            wreg[4 * i + 0] = wv.x; wreg[4 * i + 1] = wv.y;
            wreg[4 * i + 2] = wv.z; wreg[4 * i + 3] = wv.w;
        }
    }

    if (tid < 256) { h2s[0][tid] = 0.f; h2s[1][tid] = 0.f; }

    uint32_t mbar_addr;
    asm("{ .reg .u64 t; cvta.to.shared.u64 t, %1; cvt.u32.u64 %0, t; }"
        : "=r"(mbar_addr) : "l"((void*)&mbar_storage));
    if (tid == 0) {
        asm volatile("mbarrier.init.shared.b64 [%0], %1;"
                     :: "r"(mbar_addr), "r"(256) : "memory");
    }

    float* peerH = (float*)cluster.map_shared_rank((void*)h2s, peer);

    cluster.sync();

    const float* gx_row = gx + (size_t)batch * Tq * G4q + row;
    const bool write_out = (peer == rank);
    float c0 = 0.f;
    float cur = gx_row[0];

    for (int t = 0; t < Tq; t++) {
        // prefetch next-step gx before waiting (hides DRAM latency)
        float nxt = 0.f;
        if (t + 1 < Tq) nxt = gx_row[(size_t)(t + 1) * G4q];

        if (t > 0) {
            unsigned par = (unsigned)((t - 1) & 1);
            MBAR_WAIT_ACQ_CLUSTER(mbar_addr, par);
        }
        const int p = t & 1;
        const float* hb = &h2s[p][kh << 7];

        // matvec: 128 FMAs from register weights, h via LDS broadcast
        float a0 = 0.f, a1 = 0.f, a2 = 0.f, a3 = 0.f;
#pragma unroll
        for (int i = 0; i < 32; i++) {
            float4 hv = *(const float4*)(hb + 4 * i);
            a0 = fmaf(wreg[4 * i + 0], hv.x, a0);
            a1 = fmaf(wreg[4 * i + 1], hv.y, a1);
            a2 = fmaf(wreg[4 * i + 2], hv.z, a2);
            a3 = fmaf(wreg[4 * i + 3], hv.w, a3);
        }
        float partial = (a0 + a1) + (a2 + a3);
        // combine k-halves (lanes l and l^16 hold the two halves of same row)
        float sum = partial + __shfl_xor_sync(0xFFFFFFFFu, partial, 16);
        sum += cur;   // gx for this row

        // gather the 4 gate sums of unit v (lanes v, v+4, v+8, v+12)
        float si = __shfl_sync(0xFFFFFFFFu, sum, v);
        float sf = __shfl_sync(0xFFFFFFFFu, sum, v + 4);
        float sg = __shfl_sync(0xFFFFFFFFu, sum, v + 8);
        float so = __shfl_sync(0xFFFFFFFFu, sum, v + 12);

        // every lane redundantly computes h(unit v) — deterministic
        c0 = sigfast(sf) * c0 + sigfast(si) * tanhfast(sg);
        float hnew = sigfast(so) * tanhfast(c0);

        if (write_out)
            h_out[((size_t)batch * Tq + t) * Hq + gunit] = hnew;

        if (t + 1 < Tq) {
            peerH[((p ^ 1) << 8) + gunit] = hnew;   // 1 DSMEM store
            MBAR_ARRIVE_REL_CLUSTER(mbar_addr, peer); // 1 release-arrive
        }
        cur = nxt;
    }
    cluster.sync();
}

// ---------------- attention (last query row only) ----------------
__global__ __launch_bounds__(256) void attn_last(
    const float* __restrict__ qkv_w, const float* __restrict__ qkv_b)
{
    __shared__ float q[64];
    __shared__ float sc[Tq];
    __shared__ float red[256];
    __shared__ float vp[256];
    const int bh = blockIdx.x;
    const int b = bh >> 3, h = bh & 7;
    const int tid = threadIdx.x;

    if (tid < 64) {
        int row = h * 64 + tid;
        const float* wr = qkv_w + (size_t)row * Dq;
        const float* ml = g_h2 + ((size_t)b * Tq + (Tq - 1)) * Hq;
        const float* mc = g_cv + ((size_t)b * Tq + (Tq - 1)) * Hq;
        float acc = qkv_b[row];
        for (int k = 0; k < 256; k++) acc = fmaf(ml[k], wr[k], acc);
        for (int k = 0; k < 256; k++) acc = fmaf(mc[k], wr[256 + k], acc);
        q[tid] = acc * 0.125f;
    }
    __syncthreads();

    float lmax = -1e30f;
    for (int t = tid; t < Tq; t += 256) {
        const float4* kp = (const float4*)(g_kv + ((size_t)b * Tq + t) * G4q + h * 64);
        float s = 0.f;
#pragma unroll
        for (int d4 = 0; d4 < 16; d4++) {
            float4 kk = kp[d4];
            float4 qq = ((const float4*)q)[d4];
            s += kk.x * qq.x + kk.y * qq.y + kk.z * qq.z + kk.w * qq.w;
        }
        sc[t] = s;
        lmax = fmaxf(lmax, s);
    }
    red[tid] = lmax; __syncthreads();
    for (int s2 = 128; s2 > 0; s2 >>= 1) {
        if (tid < s2) red[tid] = fmaxf(red[tid], red[tid + s2]);
        __syncthreads();
    }
    float m = red[0];
    __syncthreads();

    float lsum = 0.f;
    for (int t = tid; t < Tq; t += 256) {
        float pe = __expf(sc[t] - m);
        sc[t] = pe;
        lsum += pe;
    }
    red[tid] = lsum; __syncthreads();
    for (int s2 = 128; s2 > 0; s2 >>= 1) {
        if (tid < s2) red[tid] += red[tid + s2];
        __syncthreads();
    }
    float denom = red[0];
    __syncthreads();

    const int d = tid & 63, gg = tid >> 6;
    float acc = 0.f;
    for (int t = gg * 512; t < (gg + 1) * 512; t++)
        acc = fmaf(sc[t], g_kv[((size_t)b * Tq + t) * G4q + 512 + h * 64 + d], acc);
    vp[tid] = acc; __syncthreads();
    if (tid < 64) {
        float o = (vp[tid] + vp[64 + tid] + vp[128 + tid] + vp[192 + tid]) / denom;
        g_at[b * Dq + h * 64 + tid] = o;
    }
}

// ---------------- head ----------------
__global__ __launch_bounds__(512) void head_kernel(
    const float* __restrict__ pw, const float* __restrict__ pb,
    const float* __restrict__ lng, const float* __restrict__ lnb,
    const float* __restrict__ f1w, const float* __restrict__ f1b,
    const float* __restrict__ f2w, const float* __restrict__ f2b,
    float* __restrict__ out)
{
    __shared__ float a[Dq], zn[Dq], z2[Hq], red[512];
    const int b = blockIdx.x, tid = threadIdx.x;
    a[tid] = g_at[b * Dq + tid];
    __syncthreads();

    float acc = pb[tid];
    const float* wr = pw + (size_t)tid * Dq;
    for (int k = 0; k < Dq; k++) acc = fmaf(a[k], wr[k], acc);
    float mrg = (tid < 256) ? g_h2[((size_t)b * Tq + Tq - 1) * Hq + tid]
                            : g_cv[((size_t)b * Tq + Tq - 1) * Hq + tid - 256];
    float z = acc + mrg;

    red[tid] = z; __syncthreads();
    for (int s = 256; s > 0; s >>= 1) {
        if (tid < s) red[tid] += red[tid + s];
        __syncthreads();
    }
    float mu = red[0] / 512.f;
    __syncthreads();
    float dv = z - mu;
    red[tid] = dv * dv; __syncthreads();
    for (int s = 256; s > 0; s >>= 1) {
        if (tid < s) red[tid] += red[tid + s];
        __syncthreads();
    }
    float var = red[0] / 512.f;
    __syncthreads();

    zn[tid] = dv * rsqrtf(var + EPSq) * lng[tid] + lnb[tid];
    __syncthreads();

    if (tid < 256) {
        float a2 = f1b[tid];
        const float* w1 = f1w + (size_t)tid * Dq;
        for (int k = 0; k < Dq; k++) a2 = fmaf(zn[k], w1[k], a2);
        z2[tid] = a2 / (1.f + expf(-a2));
    }
    __syncthreads();

    if (tid < 3) {
        float lg = f2b[tid];
        const float* w2 = f2w + tid * 256;
        for (int j = 0; j < 256; j++) lg = fmaf(z2[j], w2[j], lg);
        if (tid == 0)      out[b]     = tanhf(lg);
        else if (tid == 1) out[4 + b] = (lg > 20.f) ? lg : log1pf(expf(lg));
        else               out[8 + b] = 1.f / (1.f + expf(-lg));
    }
}

// ---------------- launch ----------------
extern "C" void kernel_launch(void* const* d_in, const int* in_sizes, int n_in,
                              void* d_out, int out_size) {
    const float* x     = (const float*)d_in[0];
    const float* wih0  = (const float*)d_in[1];
    const float* whh0  = (const float*)d_in[2];
    const float* bih0  = (const float*)d_in[3];
    const float* bhh0  = (const float*)d_in[4];
    const float* wih1  = (const float*)d_in[5];
    const float* whh1  = (const float*)d_in[6];
    const float* bih1  = (const float*)d_in[7];
    const float* bhh1  = (const float*)d_in[8];
    const float* cw    = (const float*)d_in[9];
    const float* cb    = (const float*)d_in[10];
    const float* bng   = (const float*)d_in[11];
    const float* bnb   = (const float*)d_in[12];
    const float* bnm   = (const float*)d_in[13];
    const float* bnv   = (const float*)d_in[14];
    const float* qkvw  = (const float*)d_in[15];
    const float* qkvb  = (const float*)d_in[16];
    const float* pw    = (const float*)d_in[17];
    const float* pbv   = (const float*)d_in[18];
    const float* lng   = (const float*)d_in[19];
    const float* lnb   = (const float*)d_in[20];
    const float* f1w   = (const float*)d_in[21];
    const float* f1b   = (const float*)d_in[22];
    const float* f2w   = (const float*)d_in[23];
    const float* f2b   = (const float*)d_in[24];
    float* out = (float*)d_out;

    float *gx0, *gx1, *h1, *h2, *cv, *kv;
    cudaGetSymbolAddress((void**)&gx0, g_gx0);
    cudaGetSymbolAddress((void**)&gx1, g_gx1);
    cudaGetSymbolAddress((void**)&h1,  g_h1);
    cudaGetSymbolAddress((void**)&h2,  g_h2);
    cudaGetSymbolAddress((void**)&cv,  g_cv);
    cudaGetSymbolAddress((void**)&kv,  g_kv);

    const int conv_smem = (36 * 64 + 64 * 321) * 4;
    cudaFuncSetAttribute(conv_bn_silu, cudaFuncAttributeMaxDynamicSharedMemorySize, conv_smem);

    // gx0 = x @ w_ih0^T + b_ih0 + b_hh0
    gemm128<<<dim3(64, 16), 256>>>(x, nullptr, 64, 64, wih0, bih0, bhh0, gx0, G4q);
    // conv branch (independent of LSTM)
    conv_bn_silu<<<dim3(64, 4, 4), 256, conv_smem>>>(x, cw, cb, bng, bnb, bnm, bnv);
    // layer-0 scan: 4 clusters (one per batch) x 8 CTAs
    lstm_scan<<<32, 256>>>(gx0, whh0, h1);
    // gx1 = h1 @ w_ih1^T + b_ih1 + b_hh1
    gemm128<<<dim3(64, 16), 256>>>(h1, nullptr, 256, 256, wih1, bih1, bhh1, gx1, G4q);
    // layer-1 scan
    lstm_scan<<<32, 256>>>(gx1, whh1, h2);
    // kv = merged @ qkv_w[512:1536]^T + qkv_b[512:1536]
    gemm128<<<dim3(64, 16), 256>>>(h2, cv, 256, 512, qkvw + 512 * 512, qkvb + 512,
                                   nullptr, kv, G4q);
    // attention (last row only)
    attn_last<<<32, 256>>>(qkvw, qkvb);
    // head
    head_kernel<<<4, 512>>>(pw, pbv, lng, lnb, f1w, f1b, f2w, f2b, out);
}

// round 6
// speedup vs baseline: 2.2617x; 1.0124x over previous
#include <cuda_runtime.h>
#include <cooperative_groups.h>
#include <math.h>

namespace cg = cooperative_groups;

#define Bq   4
#define Tq   2048
#define INq  64
#define Hq   256
#define Dq   512
#define G4q  1024
#define EPSq 1e-5f

// ---------------- static scratch ----------------
__device__ float g_gx0[Bq * Tq * G4q];
__device__ float g_gx1[Bq * Tq * G4q];
__device__ float g_h1 [Bq * Tq * Hq];
__device__ float g_h2 [Bq * Tq * Hq];
__device__ float g_cv [Bq * Tq * Hq];
__device__ float g_kv [Bq * Tq * G4q];
__device__ float g_at [Bq * Dq];

__device__ __forceinline__ float sigfast(float x) {
    return __fdividef(1.f, 1.f + __expf(-x));
}
__device__ __forceinline__ float tanhfast(float x) {
    return 1.f - __fdividef(2.f, __expf(2.f * x) + 1.f);
}

#define FMA_F32X2(d, a, b, c) \
    asm("fma.rn.f32x2 %0, %1, %2, %3;" : "=l"(d) : "l"(a), "l"(b), "l"(c))

__device__ __forceinline__ float hsum_f32x2(unsigned long long v) {
    float lo, hi;
    asm("mov.b64 {%0, %1}, %2;" : "=f"(lo), "=f"(hi) : "l"(v));
    return lo + hi;
}

// ---------------- GEMM 128x64 tiles: out[m,n] = sum_k A[m,k]*W[n,k] + b1[n](+b2[n])
__global__ __launch_bounds__(256) void gemm128(
    const float* __restrict__ A1, const float* __restrict__ A2,
    int Ksplit, int K,
    const float* __restrict__ W, const float* __restrict__ b1,
    const float* __restrict__ b2, float* __restrict__ out, int N)
{
    __shared__ float As[16][128];
    __shared__ float Bs[16][64];
    const int m0 = blockIdx.x * 128, n0 = blockIdx.y * 64;
    const int tid = threadIdx.x;
    const int tx = tid & 15, ty = tid >> 4;
    const int lmA = tid & 127, khA = (tid >> 7) * 8;
    const int lnB = tid & 63,  kB  = (tid >> 6) * 4;
    const int K2 = K - Ksplit;

    float acc[8][4];
#pragma unroll
    for (int i = 0; i < 8; i++)
#pragma unroll
        for (int j = 0; j < 4; j++) acc[i][j] = 0.f;

    for (int k0 = 0; k0 < K; k0 += 16) {
        {
            int m = m0 + lmA;
#pragma unroll
            for (int half = 0; half < 2; half++) {
                int off = khA + half * 4;
                int kg = k0 + off;
                float4 v;
                if (kg < Ksplit) v = *(const float4*)(A1 + (size_t)m * Ksplit + kg);
                else             v = *(const float4*)(A2 + (size_t)m * K2 + (kg - Ksplit));
                As[off + 0][lmA] = v.x; As[off + 1][lmA] = v.y;
                As[off + 2][lmA] = v.z; As[off + 3][lmA] = v.w;
            }
            int n = n0 + lnB;
            float4 wv = *(const float4*)(W + (size_t)n * K + k0 + kB);
            Bs[kB + 0][lnB] = wv.x; Bs[kB + 1][lnB] = wv.y;
            Bs[kB + 2][lnB] = wv.z; Bs[kB + 3][lnB] = wv.w;
        }
        __syncthreads();
#pragma unroll
        for (int kk = 0; kk < 16; kk++) {
            float4 a0 = *(const float4*)&As[kk][ty * 8];
            float4 a1 = *(const float4*)&As[kk][ty * 8 + 4];
            float4 b  = *(const float4*)&Bs[kk][tx * 4];
            float av[8] = {a0.x, a0.y, a0.z, a0.w, a1.x, a1.y, a1.z, a1.w};
#pragma unroll
            for (int i = 0; i < 8; i++) {
                acc[i][0] = fmaf(av[i], b.x, acc[i][0]);
                acc[i][1] = fmaf(av[i], b.y, acc[i][1]);
                acc[i][2] = fmaf(av[i], b.z, acc[i][2]);
                acc[i][3] = fmaf(av[i], b.w, acc[i][3]);
            }
        }
        __syncthreads();
    }

    float bias[4];
#pragma unroll
    for (int j = 0; j < 4; j++) {
        int n = n0 + tx * 4 + j;
        bias[j] = b1[n] + (b2 ? b2[n] : 0.f);
    }
#pragma unroll
    for (int i = 0; i < 8; i++) {
        int m = m0 + ty * 8 + i;
        float4 r = make_float4(acc[i][0] + bias[0], acc[i][1] + bias[1],
                               acc[i][2] + bias[2], acc[i][3] + bias[3]);
        *(float4*)(out + (size_t)m * N + n0 + tx * 4) = r;
    }
}

// ---------------- conv1d(K=5,same) + BN + SiLU ----------------
__global__ __launch_bounds__(256, 1) void conv_bn_silu(
    const float* __restrict__ x, const float* __restrict__ cw,
    const float* __restrict__ cb, const float* __restrict__ bg,
    const float* __restrict__ bnb, const float* __restrict__ bmean,
    const float* __restrict__ bvar)
{
    extern __shared__ float sm[];
    float* xs = sm;              // [36][64]
    float* ws = sm + 36 * 64;    // [64][321]
    const int b = blockIdx.z;
    const int t0 = blockIdx.x * 32;
    const int ocb = blockIdx.y * 64;
    const int tid = threadIdx.x;

    for (int idx = tid; idx < 36 * 64; idx += 256) {
        int tr = idx >> 6, i = idx & 63;
        int tg = t0 + tr - 2;
        xs[idx] = (tg >= 0 && tg < Tq) ? x[((size_t)b * Tq + tg) * INq + i] : 0.f;
    }
    for (int idx = tid; idx < 64 * 320; idx += 256) {
        int o = idx / 320, ik = idx % 320;
        ws[o * 321 + ik] = cw[(size_t)(ocb + o) * 320 + ik];
    }
    __syncthreads();

    const int o = tid & 63, gq = tid >> 6;
    const int tb = gq * 8;
    float acc[8];
#pragma unroll
    for (int t = 0; t < 8; t++) acc[t] = 0.f;

    for (int i = 0; i < 64; i++) {
        float xv[12];
#pragma unroll
        for (int j = 0; j < 12; j++) xv[j] = xs[(tb + j) * 64 + i];
#pragma unroll
        for (int k = 0; k < 5; k++) {
            float wv = ws[o * 321 + i * 5 + k];
#pragma unroll
            for (int t = 0; t < 8; t++) acc[t] = fmaf(xv[t + k], wv, acc[t]);
        }
    }
    const int oc = ocb + o;
    float scl = rsqrtf(bvar[oc] + EPSq) * bg[oc];
    float sh = bnb[oc] - bmean[oc] * scl;
    float cbv = cb[oc];
#pragma unroll
    for (int t = 0; t < 8; t++) {
        float y = (acc[t] + cbv) * scl + sh;
        g_cv[((size_t)b * Tq + t0 + tb + t) * Hq + oc] = y / (1.f + __expf(-y));
    }
}

// ---------------- mbarrier helpers ----------------
#define MBAR_WAIT_ACQ_CLUSTER(addr, par) do {                                    \
    unsigned _done;                                                              \
    asm volatile("{\n\t.reg .pred P;\n\t"                                        \
        "mbarrier.try_wait.parity.acquire.cluster.shared::cta.b64 P, [%1], %2;\n\t" \
        "selp.b32 %0, 1, 0, P;\n\t}"                                             \
        : "=r"(_done) : "r"(addr), "r"(par) : "memory");                         \
    while (!_done) {                                                             \
        asm volatile("{\n\t.reg .pred P;\n\t"                                    \
            "mbarrier.try_wait.parity.acquire.cluster.shared::cta.b64 P, [%1], %2, 0x989680;\n\t" \
            "selp.b32 %0, 1, 0, P;\n\t}"                                         \
            : "=r"(_done) : "r"(addr), "r"(par) : "memory");                     \
    }                                                                            \
} while (0)

#define MBAR_ARRIVE_REL_CLUSTER(addr, r) \
    asm volatile("{\n\t.reg .b32 ra;\n\t"                                        \
        "mapa.shared::cluster.u32 ra, %0, %1;\n\t"                               \
        "mbarrier.arrive.release.cluster.shared::cluster.b64 _, [ra];\n\t}"      \
        :: "r"(addr), "r"(r) : "memory")

// ---------------- LSTM scan: 4 clusters x 8 CTAs, one batch per cluster --------
// Register-resident weights in packed f32x2 form; warp-local gates;
// per step: 1 DSMEM store per lane, 1 aggregated arrive per (warp, dest).
__global__ void __cluster_dims__(8, 1, 1) __launch_bounds__(256, 1) lstm_scan(
    const float* __restrict__ gx, const float* __restrict__ w_hh,
    float* __restrict__ h_out)
{
    __shared__ float h2s[2][256];
    __shared__ alignas(8) unsigned long long mbar_storage;

    cg::cluster_group cluster = cg::this_cluster();
    const int rank  = (int)cluster.block_rank();
    const int batch = blockIdx.x >> 3;
    const int tid = threadIdx.x;
    const int w = tid >> 5, l = tid & 31;
    const int v  = l & 3;
    const int g  = (l >> 2) & 3;
    const int kh = l >> 4;
    const int peer = l >> 2;
    const int gunit = rank * 32 + w * 4 + v;     // global hidden unit 0..255
    const int row = g * Hq + gunit;              // gate row 0..1023

    // this thread's 128 weights, packed as 64 x f32x2 (pairs along k)
    unsigned long long wreg[64];
    {
        const ulonglong2* wp = (const ulonglong2*)(w_hh + (size_t)row * Hq + (kh << 7));
#pragma unroll
        for (int i = 0; i < 32; i++) {
            ulonglong2 t2 = wp[i];
            wreg[2 * i]     = t2.x;
            wreg[2 * i + 1] = t2.y;
        }
    }

    if (tid < 256) { h2s[0][tid] = 0.f; h2s[1][tid] = 0.f; }

    uint32_t mbar_addr;
    asm("{ .reg .u64 t; cvta.to.shared.u64 t, %1; cvt.u32.u64 %0, t; }"
        : "=r"(mbar_addr) : "l"((void*)&mbar_storage));
    if (tid == 0) {
        // 8 warps x 8 source CTAs = 64 aggregated arrives per phase
        asm volatile("mbarrier.init.shared.b64 [%0], %1;"
                     :: "r"(mbar_addr), "r"(64) : "memory");
    }

    float* peerH = (float*)cluster.map_shared_rank((void*)h2s, peer);

    cluster.sync();

    const float* gx_row = gx + (size_t)batch * Tq * G4q + row;
    const bool write_out = (peer == rank);
    float c0 = 0.f;
    float cur = gx_row[0];

    for (int t = 0; t < Tq; t++) {
        // prefetch next-step gx before waiting (hides DRAM latency)
        float nxt = 0.f;
        if (t + 1 < Tq) nxt = gx_row[(size_t)(t + 1) * G4q];

        if (t > 0) {
            unsigned par = (unsigned)((t - 1) & 1);
            MBAR_WAIT_ACQ_CLUSTER(mbar_addr, par);
        }
        const int p = t & 1;
        const ulonglong2* hb2 = (const ulonglong2*)&h2s[p][kh << 7];

        // matvec: 64 packed f32x2 FMAs, 4 independent chains
        unsigned long long acc0 = 0ull, acc1 = 0ull, acc2 = 0ull, acc3 = 0ull;
#pragma unroll
        for (int i = 0; i < 32; i += 2) {
            ulonglong2 hv0 = hb2[i];
            ulonglong2 hv1 = hb2[i + 1];
            FMA_F32X2(acc0, wreg[2 * i + 0], hv0.x, acc0);
            FMA_F32X2(acc1, wreg[2 * i + 1], hv0.y, acc1);
            FMA_F32X2(acc2, wreg[2 * i + 2], hv1.x, acc2);
            FMA_F32X2(acc3, wreg[2 * i + 3], hv1.y, acc3);
        }
        float partial = (hsum_f32x2(acc0) + hsum_f32x2(acc1))
                      + (hsum_f32x2(acc2) + hsum_f32x2(acc3));
        // combine k-halves (lanes l and l^16 hold the two halves of same row)
        float sum = partial + __shfl_xor_sync(0xFFFFFFFFu, partial, 16);
        sum += cur;   // gx for this row

        // gather the 4 gate sums of unit v (lanes v, v+4, v+8, v+12)
        float si = __shfl_sync(0xFFFFFFFFu, sum, v);
        float sf = __shfl_sync(0xFFFFFFFFu, sum, v + 4);
        float sg = __shfl_sync(0xFFFFFFFFu, sum, v + 8);
        float so = __shfl_sync(0xFFFFFFFFu, sum, v + 12);

        // every lane redundantly computes h(unit v) — deterministic
        c0 = sigfast(sf) * c0 + sigfast(si) * tanhfast(sg);
        float hnew = sigfast(so) * tanhfast(c0);

        if (write_out)
            h_out[((size_t)batch * Tq + t) * Hq + gunit] = hnew;

        if (t + 1 < Tq) {
            peerH[((p ^ 1) << 8) + gunit] = hnew;   // 1 DSMEM store per lane
            __syncwarp();                            // order lanes' stores
            if (l < 8) MBAR_ARRIVE_REL_CLUSTER(mbar_addr, l); // 1 arrive/warp/dest
        }
        cur = nxt;
    }
    cluster.sync();
}

// ---------------- attention (last query row only) ----------------
__global__ __launch_bounds__(256) void attn_last(
    const float* __restrict__ qkv_w, const float* __restrict__ qkv_b)
{
    __shared__ float q[64];
    __shared__ float sc[Tq];
    __shared__ float red[256];
    __shared__ float vp[256];
    const int bh = blockIdx.x;
    const int b = bh >> 3, h = bh & 7;
    const int tid = threadIdx.x;

    if (tid < 64) {
        int row = h * 64 + tid;
        const float* wr = qkv_w + (size_t)row * Dq;
        const float* ml = g_h2 + ((size_t)b * Tq + (Tq - 1)) * Hq;
        const float* mc = g_cv + ((size_t)b * Tq + (Tq - 1)) * Hq;
        float acc = qkv_b[row];
        for (int k = 0; k < 256; k++) acc = fmaf(ml[k], wr[k], acc);
        for (int k = 0; k < 256; k++) acc = fmaf(mc[k], wr[256 + k], acc);
        q[tid] = acc * 0.125f;
    }
    __syncthreads();

    float lmax = -1e30f;
    for (int t = tid; t < Tq; t += 256) {
        const float4* kp = (const float4*)(g_kv + ((size_t)b * Tq + t) * G4q + h * 64);
        float s = 0.f;
#pragma unroll
        for (int d4 = 0; d4 < 16; d4++) {
            float4 kk = kp[d4];
            float4 qq = ((const float4*)q)[d4];
            s += kk.x * qq.x + kk.y * qq.y + kk.z * qq.z + kk.w * qq.w;
        }
        sc[t] = s;
        lmax = fmaxf(lmax, s);
    }
    red[tid] = lmax; __syncthreads();
    for (int s2 = 128; s2 > 0; s2 >>= 1) {
        if (tid < s2) red[tid] = fmaxf(red[tid], red[tid + s2]);
        __syncthreads();
    }
    float m = red[0];
    __syncthreads();

    float lsum = 0.f;
    for (int t = tid; t < Tq; t += 256) {
        float pe = __expf(sc[t] - m);
        sc[t] = pe;
        lsum += pe;
    }
    red[tid] = lsum; __syncthreads();
    for (int s2 = 128; s2 > 0; s2 >>= 1) {
        if (tid < s2) red[tid] += red[tid + s2];
        __syncthreads();
    }
    float denom = red[0];
    __syncthreads();

    const int d = tid & 63, gg = tid >> 6;
    float acc = 0.f;
    for (int t = gg * 512; t < (gg + 1) * 512; t++)
        acc = fmaf(sc[t], g_kv[((size_t)b * Tq + t) * G4q + 512 + h * 64 + d], acc);
    vp[tid] = acc; __syncthreads();
    if (tid < 64) {
        float o = (vp[tid] + vp[64 + tid] + vp[128 + tid] + vp[192 + tid]) / denom;
        g_at[b * Dq + h * 64 + tid] = o;
    }
}

// ---------------- head ----------------
__global__ __launch_bounds__(512) void head_kernel(
    const float* __restrict__ pw, const float* __restrict__ pb,
    const float* __restrict__ lng, const float* __restrict__ lnb,
    const float* __restrict__ f1w, const float* __restrict__ f1b,
    const float* __restrict__ f2w, const float* __restrict__ f2b,
    float* __restrict__ out)
{
    __shared__ float a[Dq], zn[Dq], z2[Hq], red[512];
    const int b = blockIdx.x, tid = threadIdx.x;
    a[tid] = g_at[b * Dq + tid];
    __syncthreads();

    float acc = pb[tid];
    const float* wr = pw + (size_t)tid * Dq;
    for (int k = 0; k < Dq; k++) acc = fmaf(a[k], wr[k], acc);
    float mrg = (tid < 256) ? g_h2[((size_t)b * Tq + Tq - 1) * Hq + tid]
                            : g_cv[((size_t)b * Tq + Tq - 1) * Hq + tid - 256];
    float z = acc + mrg;

    red[tid] = z; __syncthreads();
    for (int s = 256; s > 0; s >>= 1) {
        if (tid < s) red[tid] += red[tid + s];
        __syncthreads();
    }
    float mu = red[0] / 512.f;
    __syncthreads();
    float dv = z - mu;
    red[tid] = dv * dv; __syncthreads();
    for (int s = 256; s > 0; s >>= 1) {
        if (tid < s) red[tid] += red[tid + s];
        __syncthreads();
    }
    float var = red[0] / 512.f;
    __syncthreads();

    zn[tid] = dv * rsqrtf(var + EPSq) * lng[tid] + lnb[tid];
    __syncthreads();

    if (tid < 256) {
        float a2 = f1b[tid];
        const float* w1 = f1w + (size_t)tid * Dq;
        for (int k = 0; k < Dq; k++) a2 = fmaf(zn[k], w1[k], a2);
        z2[tid] = a2 / (1.f + expf(-a2));
    }
    __syncthreads();

    if (tid < 3) {
        float lg = f2b[tid];
        const float* w2 = f2w + tid * 256;
        for (int j = 0; j < 256; j++) lg = fmaf(z2[j], w2[j], lg);
        if (tid == 0)      out[b]     = tanhf(lg);
        else if (tid == 1) out[4 + b] = (lg > 20.f) ? lg : log1pf(expf(lg));
        else               out[8 + b] = 1.f / (1.f + expf(-lg));
    }
}

// ---------------- launch ----------------
extern "C" void kernel_launch(void* const* d_in, const int* in_sizes, int n_in,
                              void* d_out, int out_size) {
    const float* x     = (const float*)d_in[0];
    const float* wih0  = (const float*)d_in[1];
    const float* whh0  = (const float*)d_in[2];
    const float* bih0  = (const float*)d_in[3];
    const float* bhh0  = (const float*)d_in[4];
    const float* wih1  = (const float*)d_in[5];
    const float* whh1  = (const float*)d_in[6];
    const float* bih1  = (const float*)d_in[7];
    const float* bhh1  = (const float*)d_in[8];
    const float* cw    = (const float*)d_in[9];
    const float* cb    = (const float*)d_in[10];
    const float* bng   = (const float*)d_in[11];
    const float* bnb   = (const float*)d_in[12];
    const float* bnm   = (const float*)d_in[13];
    const float* bnv   = (const float*)d_in[14];
    const float* qkvw  = (const float*)d_in[15];
    const float* qkvb  = (const float*)d_in[16];
    const float* pw    = (const float*)d_in[17];
    const float* pbv   = (const float*)d_in[18];
    const float* lng   = (const float*)d_in[19];
    const float* lnb   = (const float*)d_in[20];
    const float* f1w   = (const float*)d_in[21];
    const float* f1b   = (const float*)d_in[22];
    const float* f2w   = (const float*)d_in[23];
    const float* f2b   = (const float*)d_in[24];
    float* out = (float*)d_out;

    float *gx0, *gx1, *h1, *h2, *cv, *kv;
    cudaGetSymbolAddress((void**)&gx0, g_gx0);
    cudaGetSymbolAddress((void**)&gx1, g_gx1);
    cudaGetSymbolAddress((void**)&h1,  g_h1);
    cudaGetSymbolAddress((void**)&h2,  g_h2);
    cudaGetSymbolAddress((void**)&cv,  g_cv);
    cudaGetSymbolAddress((void**)&kv,  g_kv);

    const int conv_smem = (36 * 64 + 64 * 321) * 4;
    cudaFuncSetAttribute(conv_bn_silu, cudaFuncAttributeMaxDynamicSharedMemorySize, conv_smem);

    // gx0 = x @ w_ih0^T + b_ih0 + b_hh0
    gemm128<<<dim3(64, 16), 256>>>(x, nullptr, 64, 64, wih0, bih0, bhh0, gx0, G4q);
    // conv branch (independent of LSTM)
    conv_bn_silu<<<dim3(64, 4, 4), 256, conv_smem>>>(x, cw, cb, bng, bnb, bnm, bnv);
    // layer-0 scan: 4 clusters (one per batch) x 8 CTAs
    lstm_scan<<<32, 256>>>(gx0, whh0, h1);
    // gx1 = h1 @ w_ih1^T + b_ih1 + b_hh1
    gemm128<<<dim3(64, 16), 256>>>(h1, nullptr, 256, 256, wih1, bih1, bhh1, gx1, G4q);
    // layer-1 scan
    lstm_scan<<<32, 256>>>(gx1, whh1, h2);
    // kv = merged @ qkv_w[512:1536]^T + qkv_b[512:1536]
    gemm128<<<dim3(64, 16), 256>>>(h2, cv, 256, 512, qkvw + 512 * 512, qkvb + 512,
                                   nullptr, kv, G4q);
    // attention (last row only)
    attn_last<<<32, 256>>>(qkvw, qkvb);
    // head
    head_kernel<<<4, 512>>>(pw, pbv, lng, lnb, f1w, f1b, f2w, f2b, out);
}

// round 7
// speedup vs baseline: 3.5846x; 1.5849x over previous
#include <cuda_runtime.h>
#include <cooperative_groups.h>
#include <math.h>

namespace cg = cooperative_groups;

#define Bq   4
#define Tq   2048
#define INq  64
#define Hq   256
#define Dq   512
#define G4q  1024
#define EPSq 1e-5f

// ---------------- static scratch ----------------
__device__ float g_gx0[Bq * Tq * G4q];
__device__ float g_gx1[Bq * Tq * G4q];
__device__ float g_h1 [Bq * Tq * Hq];
__device__ float g_h2 [Bq * Tq * Hq];
__device__ float g_cv [Bq * Tq * Hq];
__device__ float g_kv [Bq * Tq * G4q];
__device__ float g_at [Bq * Dq];

__device__ __forceinline__ float sigfast(float x) {
    return __fdividef(1.f, 1.f + __expf(-x));
}
__device__ __forceinline__ float tanhfast(float x) {
    return 1.f - __fdividef(2.f, __expf(2.f * x) + 1.f);
}

#define FMA_F32X2(d, a, b, c) \
    asm("fma.rn.f32x2 %0, %1, %2, %3;" : "=l"(d) : "l"(a), "l"(b), "l"(c))

__device__ __forceinline__ float hsum_f32x2(unsigned long long v) {
    float lo, hi;
    asm("mov.b64 {%0, %1}, %2;" : "=f"(lo), "=f"(hi) : "l"(v));
    return lo + hi;
}

// ---------------- GEMM 128x64 tiles ----------------
__global__ __launch_bounds__(256) void gemm128(
    const float* __restrict__ A1, const float* __restrict__ A2,
    int Ksplit, int K,
    const float* __restrict__ W, const float* __restrict__ b1,
    const float* __restrict__ b2, float* __restrict__ out, int N)
{
    __shared__ float As[16][128];
    __shared__ float Bs[16][64];
    const int m0 = blockIdx.x * 128, n0 = blockIdx.y * 64;
    const int tid = threadIdx.x;
    const int tx = tid & 15, ty = tid >> 4;
    const int lmA = tid & 127, khA = (tid >> 7) * 8;
    const int lnB = tid & 63,  kB  = (tid >> 6) * 4;
    const int K2 = K - Ksplit;

    float acc[8][4];
#pragma unroll
    for (int i = 0; i < 8; i++)
#pragma unroll
        for (int j = 0; j < 4; j++) acc[i][j] = 0.f;

    for (int k0 = 0; k0 < K; k0 += 16) {
        {
            int m = m0 + lmA;
#pragma unroll
            for (int half = 0; half < 2; half++) {
                int off = khA + half * 4;
                int kg = k0 + off;
                float4 v;
                if (kg < Ksplit) v = *(const float4*)(A1 + (size_t)m * Ksplit + kg);
                else             v = *(const float4*)(A2 + (size_t)m * K2 + (kg - Ksplit));
                As[off + 0][lmA] = v.x; As[off + 1][lmA] = v.y;
                As[off + 2][lmA] = v.z; As[off + 3][lmA] = v.w;
            }
            int n = n0 + lnB;
            float4 wv = *(const float4*)(W + (size_t)n * K + k0 + kB);
            Bs[kB + 0][lnB] = wv.x; Bs[kB + 1][lnB] = wv.y;
            Bs[kB + 2][lnB] = wv.z; Bs[kB + 3][lnB] = wv.w;
        }
        __syncthreads();
#pragma unroll
        for (int kk = 0; kk < 16; kk++) {
            float4 a0 = *(const float4*)&As[kk][ty * 8];
            float4 a1 = *(const float4*)&As[kk][ty * 8 + 4];
            float4 b  = *(const float4*)&Bs[kk][tx * 4];
            float av[8] = {a0.x, a0.y, a0.z, a0.w, a1.x, a1.y, a1.z, a1.w};
#pragma unroll
            for (int i = 0; i < 8; i++) {
                acc[i][0] = fmaf(av[i], b.x, acc[i][0]);
                acc[i][1] = fmaf(av[i], b.y, acc[i][1]);
                acc[i][2] = fmaf(av[i], b.z, acc[i][2]);
                acc[i][3] = fmaf(av[i], b.w, acc[i][3]);
            }
        }
        __syncthreads();
    }

    float bias[4];
#pragma unroll
    for (int j = 0; j < 4; j++) {
        int n = n0 + tx * 4 + j;
        bias[j] = b1[n] + (b2 ? b2[n] : 0.f);
    }
#pragma unroll
    for (int i = 0; i < 8; i++) {
        int m = m0 + ty * 8 + i;
        float4 r = make_float4(acc[i][0] + bias[0], acc[i][1] + bias[1],
                               acc[i][2] + bias[2], acc[i][3] + bias[3]);
        *(float4*)(out + (size_t)m * N + n0 + tx * 4) = r;
    }
}

// ---------------- conv1d(K=5,same) + BN + SiLU ----------------
__global__ __launch_bounds__(256, 1) void conv_bn_silu(
    const float* __restrict__ x, const float* __restrict__ cw,
    const float* __restrict__ cb, const float* __restrict__ bg,
    const float* __restrict__ bnb, const float* __restrict__ bmean,
    const float* __restrict__ bvar)
{
    extern __shared__ float sm[];
    float* xs = sm;              // [36][64]
    float* ws = sm + 36 * 64;    // [64][321]
    const int b = blockIdx.z;
    const int t0 = blockIdx.x * 32;
    const int ocb = blockIdx.y * 64;
    const int tid = threadIdx.x;

    for (int idx = tid; idx < 36 * 64; idx += 256) {
        int tr = idx >> 6, i = idx & 63;
        int tg = t0 + tr - 2;
        xs[idx] = (tg >= 0 && tg < Tq) ? x[((size_t)b * Tq + tg) * INq + i] : 0.f;
    }
    for (int idx = tid; idx < 64 * 320; idx += 256) {
        int o = idx / 320, ik = idx % 320;
        ws[o * 321 + ik] = cw[(size_t)(ocb + o) * 320 + ik];
    }
    __syncthreads();

    const int o = tid & 63, gq = tid >> 6;
    const int tb = gq * 8;
    float acc[8];
#pragma unroll
    for (int t = 0; t < 8; t++) acc[t] = 0.f;

    for (int i = 0; i < 64; i++) {
        float xv[12];
#pragma unroll
        for (int j = 0; j < 12; j++) xv[j] = xs[(tb + j) * 64 + i];
#pragma unroll
        for (int k = 0; k < 5; k++) {
            float wv = ws[o * 321 + i * 5 + k];
#pragma unroll
            for (int t = 0; t < 8; t++) acc[t] = fmaf(xv[t + k], wv, acc[t]);
        }
    }
    const int oc = ocb + o;
    float scl = rsqrtf(bvar[oc] + EPSq) * bg[oc];
    float sh = bnb[oc] - bmean[oc] * scl;
    float cbv = cb[oc];
#pragma unroll
    for (int t = 0; t < 8; t++) {
        float y = (acc[t] + cbv) * scl + sh;
        g_cv[((size_t)b * Tq + t0 + tb + t) * Hq + oc] = y / (1.f + __expf(-y));
    }
}

// ---------------- mbarrier / st.async helpers ----------------
#define MBAR_WAIT_ACQ_CLUSTER(addr, par) do {                                    \
    unsigned _done;                                                              \
    asm volatile("{\n\t.reg .pred P;\n\t"                                        \
        "mbarrier.try_wait.parity.acquire.cluster.shared::cta.b64 P, [%1], %2;\n\t" \
        "selp.b32 %0, 1, 0, P;\n\t}"                                             \
        : "=r"(_done) : "r"(addr), "r"(par) : "memory");                         \
    while (!_done) {                                                             \
        asm volatile("{\n\t.reg .pred P;\n\t"                                    \
            "mbarrier.try_wait.parity.acquire.cluster.shared::cta.b64 P, [%1], %2, 0x989680;\n\t" \
            "selp.b32 %0, 1, 0, P;\n\t}"                                         \
            : "=r"(_done) : "r"(addr), "r"(par) : "memory");                     \
    }                                                                            \
} while (0)

#define MBAR_ARM(addr, bytes) \
    asm volatile("mbarrier.arrive.expect_tx.shared.b64 _, [%0], %1;"             \
                 :: "r"(addr), "r"(bytes) : "memory")

#define ST_ASYNC_B64(daddr, val, mbaraddr) \
    asm volatile("st.async.weak.shared::cluster.mbarrier::complete_tx::bytes.b64 [%0], %1, [%2];" \
                 :: "r"(daddr), "l"(val), "r"(mbaraddr) : "memory")

__device__ __forceinline__ uint32_t smem_u32(const void* p) {
    uint32_t a;
    asm("{ .reg .u64 t; cvta.to.shared.u64 t, %1; cvt.u32.u64 %0, t; }"
        : "=r"(a) : "l"(p));
    return a;
}
__device__ __forceinline__ uint32_t mapa_u32(uint32_t a, int r) {
    uint32_t o;
    asm("mapa.shared::cluster.u32 %0, %1, %2;" : "=r"(o) : "r"(a), "r"(r));
    return o;
}

// ---------------- LSTM scan: 4 clusters x 8 CTAs, one batch per cluster --------
// Register-resident packed weights; warp-local gates; h broadcast via
// st.async.b64 with tx-count barriers (fused data+signal, no separate arrives).
// Two mbarriers alternate even/odd steps so producers may run 1 step ahead.
__global__ void __cluster_dims__(8, 1, 1) __launch_bounds__(256, 1) lstm_scan(
    const float* __restrict__ gx, const float* __restrict__ w_hh,
    float* __restrict__ h_out)
{
    __shared__ alignas(16) float h2s[2][256];
    __shared__ alignas(16) unsigned long long mbars[2];

    cg::cluster_group cluster = cg::this_cluster();
    const int rank  = (int)cluster.block_rank();
    const int batch = blockIdx.x >> 3;
    const int tid = threadIdx.x;
    const int w = tid >> 5, l = tid & 31;
    const int v  = l & 3;
    const int g  = (l >> 2) & 3;
    const int kh = l >> 4;
    const int peer = l >> 2;
    const int gunit = rank * 32 + w * 4 + v;     // global hidden unit 0..255
    const int row = g * Hq + gunit;              // gate row 0..1023

    // this thread's 128 weights, packed as 64 x f32x2 (pairs along k)
    unsigned long long wreg[64];
    {
        const ulonglong2* wp = (const ulonglong2*)(w_hh + (size_t)row * Hq + (kh << 7));
#pragma unroll
        for (int i = 0; i < 32; i++) {
            ulonglong2 t2 = wp[i];
            wreg[2 * i]     = t2.x;
            wreg[2 * i + 1] = t2.y;
        }
    }

    if (tid < 256) { h2s[0][tid] = 0.f; h2s[1][tid] = 0.f; }

    const uint32_t mb0 = smem_u32(&mbars[0]);
    const uint32_t mb1 = smem_u32(&mbars[1]);
    if (tid == 0) {
        asm volatile("mbarrier.init.shared.b64 [%0], 1;" :: "r"(mb0) : "memory");
        asm volatile("mbarrier.init.shared.b64 [%0], 1;" :: "r"(mb1) : "memory");
        // arm step 1 (mbars[1]) and step 2 (mbars[0]); each phase = 1024 bytes
        MBAR_ARM(mb1, 1024);
        MBAR_ARM(mb0, 1024);
    }

    // peer addresses for this lane's destination CTA (even lanes send pairs)
    const uint32_t h0_local = smem_u32(&h2s[0][0]);
    uint32_t peer_h[2], peer_mb[2];
    {
        uint32_t base = mapa_u32(h0_local, peer);
        peer_h[0] = base + (uint32_t)(gunit * 4);          // buffer 0, this unit pair
        peer_h[1] = base + (uint32_t)(256 * 4 + gunit * 4);
        peer_mb[0] = mapa_u32(mb0, peer);
        peer_mb[1] = mapa_u32(mb1, peer);
    }

    cluster.sync();

    const float* gx_row = gx + (size_t)batch * Tq * G4q + row;
    const bool write_out = (peer == rank);
    const bool sender = ((l & 1) == 0);   // lanes with even v send (v, v+1) as b64
    float c0 = 0.f;
    float cur = gx_row[0];

    for (int t = 0; t < Tq; t++) {
        // prefetch next-step gx before waiting (hides DRAM latency)
        float nxt = 0.f;
        if (t + 1 < Tq) nxt = gx_row[(size_t)(t + 1) * G4q];

        if (t > 0) {
            const uint32_t mb = (t & 1) ? mb1 : mb0;
            unsigned par = (unsigned)(((t >> 1) + ((t & 1) ^ 1)) & 1);
            MBAR_WAIT_ACQ_CLUSTER(mb, par);
            // re-arm this mbar for step t+2. Safe: this arm happens before this
            // CTA sends its h(t+1) (tid0 program order below), and any producer's
            // t+2 stores require all h(t+1) including ours -> arm happens-before.
            if (tid == 0 && t + 2 < Tq) MBAR_ARM(mb, 1024);
        }
        const int p = t & 1;
        const ulonglong2* hb2 = (const ulonglong2*)&h2s[p][kh << 7];

        // matvec: 64 packed f32x2 FMAs, 4 independent chains
        unsigned long long acc0 = 0ull, acc1 = 0ull, acc2 = 0ull, acc3 = 0ull;
#pragma unroll
        for (int i = 0; i < 32; i += 2) {
            ulonglong2 hv0 = hb2[i];
            ulonglong2 hv1 = hb2[i + 1];
            FMA_F32X2(acc0, wreg[2 * i + 0], hv0.x, acc0);
            FMA_F32X2(acc1, wreg[2 * i + 1], hv0.y, acc1);
            FMA_F32X2(acc2, wreg[2 * i + 2], hv1.x, acc2);
            FMA_F32X2(acc3, wreg[2 * i + 3], hv1.y, acc3);
        }
        float partial = (hsum_f32x2(acc0) + hsum_f32x2(acc1))
                      + (hsum_f32x2(acc2) + hsum_f32x2(acc3));
        // combine k-halves (lanes l and l^16 hold the two halves of same row)
        float sum = partial + __shfl_xor_sync(0xFFFFFFFFu, partial, 16);
        sum += cur;   // gx for this row

        // gather the 4 gate sums of unit v (lanes v, v+4, v+8, v+12)
        float si = __shfl_sync(0xFFFFFFFFu, sum, v);
        float sf = __shfl_sync(0xFFFFFFFFu, sum, v + 4);
        float sg = __shfl_sync(0xFFFFFFFFu, sum, v + 8);
        float so = __shfl_sync(0xFFFFFFFFu, sum, v + 12);

        // every lane redundantly computes h(unit v) — deterministic
        c0 = sigfast(sf) * c0 + sigfast(si) * tanhfast(sg);
        float hnew = sigfast(so) * tanhfast(c0);

        if (write_out)
            h_out[((size_t)batch * Tq + t) * Hq + gunit] = hnew;

        if (t + 1 < Tq) {
            // pair (v even): units v and v+1 packed into one b64 st.async
            float hpartner = __shfl_xor_sync(0xFFFFFFFFu, hnew, 1);
            if (sender) {
                unsigned long long pk;
                asm("mov.b64 %0, {%1, %2};" : "=l"(pk) : "f"(hnew), "f"(hpartner));
                const int q = (t + 1) & 1;
                ST_ASYNC_B64(peer_h[q], pk, peer_mb[q]);
            }
        }
        cur = nxt;
    }
    cluster.sync();
}

// ---------------- no-op spacer (aligns ncu -s 5 onto scan1) ----------------
__global__ void noop_k() {}

// ---------------- attention (last query row only) ----------------
__global__ __launch_bounds__(256) void attn_last(
    const float* __restrict__ qkv_w, const float* __restrict__ qkv_b)
{
    __shared__ float q[64];
    __shared__ float sc[Tq];
    __shared__ float red[256];
    __shared__ float vp[256];
    const int bh = blockIdx.x;
    const int b = bh >> 3, h = bh & 7;
    const int tid = threadIdx.x;

    if (tid < 64) {
        int row = h * 64 + tid;
        const float* wr = qkv_w + (size_t)row * Dq;
        const float* ml = g_h2 + ((size_t)b * Tq + (Tq - 1)) * Hq;
        const float* mc = g_cv + ((size_t)b * Tq + (Tq - 1)) * Hq;
        float acc = qkv_b[row];
        for (int k = 0; k < 256; k++) acc = fmaf(ml[k], wr[k], acc);
        for (int k = 0; k < 256; k++) acc = fmaf(mc[k], wr[256 + k], acc);
        q[tid] = acc * 0.125f;
    }
    __syncthreads();

    float lmax = -1e30f;
    for (int t = tid; t < Tq; t += 256) {
        const float4* kp = (const float4*)(g_kv + ((size_t)b * Tq + t) * G4q + h * 64);
        float s = 0.f;
#pragma unroll
        for (int d4 = 0; d4 < 16; d4++) {
            float4 kk = kp[d4];
            float4 qq = ((const float4*)q)[d4];
            s += kk.x * qq.x + kk.y * qq.y + kk.z * qq.z + kk.w * qq.w;
        }
        sc[t] = s;
        lmax = fmaxf(lmax, s);
    }
    red[tid] = lmax; __syncthreads();
    for (int s2 = 128; s2 > 0; s2 >>= 1) {
        if (tid < s2) red[tid] = fmaxf(red[tid], red[tid + s2]);
        __syncthreads();
    }
    float m = red[0];
    __syncthreads();

    float lsum = 0.f;
    for (int t = tid; t < Tq; t += 256) {
        float pe = __expf(sc[t] - m);
        sc[t] = pe;
        lsum += pe;
    }
    red[tid] = lsum; __syncthreads();
    for (int s2 = 128; s2 > 0; s2 >>= 1) {
        if (tid < s2) red[tid] += red[tid + s2];
        __syncthreads();
    }
    float denom = red[0];
    __syncthreads();

    const int d = tid & 63, gg = tid >> 6;
    float acc = 0.f;
    for (int t = gg * 512; t < (gg + 1) * 512; t++)
        acc = fmaf(sc[t], g_kv[((size_t)b * Tq + t) * G4q + 512 + h * 64 + d], acc);
    vp[tid] = acc; __syncthreads();
    if (tid < 64) {
        float o = (vp[tid] + vp[64 + tid] + vp[128 + tid] + vp[192 + tid]) / denom;
        g_at[b * Dq + h * 64 + tid] = o;
    }
}

// ---------------- head ----------------
__global__ __launch_bounds__(512) void head_kernel(
    const float* __restrict__ pw, const float* __restrict__ pb,
    const float* __restrict__ lng, const float* __restrict__ lnb,
    const float* __restrict__ f1w, const float* __restrict__ f1b,
    const float* __restrict__ f2w, const float* __restrict__ f2b,
    float* __restrict__ out)
{
    __shared__ float a[Dq], zn[Dq], z2[Hq], red[512];
    const int b = blockIdx.x, tid = threadIdx.x;
    a[tid] = g_at[b * Dq + tid];
    __syncthreads();

    float acc = pb[tid];
    const float* wr = pw + (size_t)tid * Dq;
    for (int k = 0; k < Dq; k++) acc = fmaf(a[k], wr[k], acc);
    float mrg = (tid < 256) ? g_h2[((size_t)b * Tq + Tq - 1) * Hq + tid]
                            : g_cv[((size_t)b * Tq + Tq - 1) * Hq + tid - 256];
    float z = acc + mrg;

    red[tid] = z; __syncthreads();
    for (int s = 256; s > 0; s >>= 1) {
        if (tid < s) red[tid] += red[tid + s];
        __syncthreads();
    }
    float mu = red[0] / 512.f;
    __syncthreads();
    float dv = z - mu;
    red[tid] = dv * dv; __syncthreads();
    for (int s = 256; s > 0; s >>= 1) {
        if (tid < s) red[tid] += red[tid + s];
        __syncthreads();
    }
    float var = red[0] / 512.f;
    __syncthreads();

    zn[tid] = dv * rsqrtf(var + EPSq) * lng[tid] + lnb[tid];
    __syncthreads();

    if (tid < 256) {
        float a2 = f1b[tid];
        const float* w1 = f1w + (size_t)tid * Dq;
        for (int k = 0; k < Dq; k++) a2 = fmaf(zn[k], w1[k], a2);
        z2[tid] = a2 / (1.f + expf(-a2));
    }
    __syncthreads();

    if (tid < 3) {
        float lg = f2b[tid];
        const float* w2 = f2w + tid * 256;
        for (int j = 0; j < 256; j++) lg = fmaf(z2[j], w2[j], lg);
        if (tid == 0)      out[b]     = tanhf(lg);
        else if (tid == 1) out[4 + b] = (lg > 20.f) ? lg : log1pf(expf(lg));
        else               out[8 + b] = 1.f / (1.f + expf(-lg));
    }
}

// ---------------- launch ----------------
extern "C" void kernel_launch(void* const* d_in, const int* in_sizes, int n_in,
                              void* d_out, int out_size) {
    const float* x     = (const float*)d_in[0];
    const float* wih0  = (const float*)d_in[1];
    const float* whh0  = (const float*)d_in[2];
    const float* bih0  = (const float*)d_in[3];
    const float* bhh0  = (const float*)d_in[4];
    const float* wih1  = (const float*)d_in[5];
    const float* whh1  = (const float*)d_in[6];
    const float* bih1  = (const float*)d_in[7];
    const float* bhh1  = (const float*)d_in[8];
    const float* cw    = (const float*)d_in[9];
    const float* cb    = (const float*)d_in[10];
    const float* bng   = (const float*)d_in[11];
    const float* bnb   = (const float*)d_in[12];
    const float* bnm   = (const float*)d_in[13];
    const float* bnv   = (const float*)d_in[14];
    const float* qkvw  = (const float*)d_in[15];
    const float* qkvb  = (const float*)d_in[16];
    const float* pw    = (const float*)d_in[17];
    const float* pbv   = (const float*)d_in[18];
    const float* lng   = (const float*)d_in[19];
    const float* lnb   = (const float*)d_in[20];
    const float* f1w   = (const float*)d_in[21];
    const float* f1b   = (const float*)d_in[22];
    const float* f2w   = (const float*)d_in[23];
    const float* f2b   = (const float*)d_in[24];
    float* out = (float*)d_out;

    float *gx0, *gx1, *h1, *h2, *cv, *kv;
    cudaGetSymbolAddress((void**)&gx0, g_gx0);
    cudaGetSymbolAddress((void**)&gx1, g_gx1);
    cudaGetSymbolAddress((void**)&h1,  g_h1);
    cudaGetSymbolAddress((void**)&h2,  g_h2);
    cudaGetSymbolAddress((void**)&cv,  g_cv);
    cudaGetSymbolAddress((void**)&kv,  g_kv);

    const int conv_smem = (36 * 64 + 64 * 321) * 4;
    cudaFuncSetAttribute(conv_bn_silu, cudaFuncAttributeMaxDynamicSharedMemorySize, conv_smem);

    // 0: gx0 = x @ w_ih0^T + b_ih0 + b_hh0
    gemm128<<<dim3(64, 16), 256>>>(x, nullptr, 64, 64, wih0, bih0, bhh0, gx0, G4q);
    // 1: conv branch (independent of LSTM)
    conv_bn_silu<<<dim3(64, 4, 4), 256, conv_smem>>>(x, cw, cb, bng, bnb, bnm, bnv);
    // 2: layer-0 scan: 4 clusters (one per batch) x 8 CTAs
    lstm_scan<<<32, 256>>>(gx0, whh0, h1);
    // 3: gx1 = h1 @ w_ih1^T + b_ih1 + b_hh1
    gemm128<<<dim3(64, 16), 256>>>(h1, nullptr, 256, 256, wih1, bih1, bhh1, gx1, G4q);
    // 4: spacer so ncu (-s 5 -c 1) captures the scan next
    noop_k<<<1, 32>>>();
    // 5: layer-1 scan  <-- profiled launch
    lstm_scan<<<32, 256>>>(gx1, whh1, h2);
    // 6: kv = merged @ qkv_w[512:1536]^T + qkv_b[512:1536]
    gemm128<<<dim3(64, 16), 256>>>(h2, cv, 256, 512, qkvw + 512 * 512, qkvb + 512,
                                   nullptr, kv, G4q);
    // 7: attention (last row only)
    attn_last<<<32, 256>>>(qkvw, qkvb);
    // 8: head
    head_kernel<<<4, 512>>>(pw, pbv, lng, lnb, f1w, f1b, f2w, f2b, out);
}

// round 8
// speedup vs baseline: 3.7765x; 1.0535x over previous
#include <cuda_runtime.h>
#include <cooperative_groups.h>
#include <math.h>

namespace cg = cooperative_groups;

#define Bq   4
#define Tq   2048
#define INq  64
#define Hq   256
#define Dq   512
#define G4q  1024
#define EPSq 1e-5f

// ---------------- static scratch ----------------
__device__ float g_gx0[Bq * Tq * G4q];
__device__ float g_gx1[Bq * Tq * G4q];
__device__ float g_h1 [Bq * Tq * Hq];
__device__ float g_h2 [Bq * Tq * Hq];
__device__ float g_cv [Bq * Tq * Hq];
__device__ float g_kv [Bq * Tq * G4q];
__device__ float g_at [Bq * Dq];

#define FMA_F32X2(d, a, b, c) \
    asm("fma.rn.f32x2 %0, %1, %2, %3;" : "=l"(d) : "l"(a), "l"(b), "l"(c))

__device__ __forceinline__ float hsum_f32x2(unsigned long long v) {
    float lo, hi;
    asm("mov.b64 {%0, %1}, %2;" : "=f"(lo), "=f"(hi) : "l"(v));
    return lo + hi;
}

// single-MUFU tanh (sm_75+); sigmoid via tanh identity
__device__ __forceinline__ float tanha(float x) {
    float y; asm("tanh.approx.f32 %0, %1;" : "=f"(y) : "f"(x)); return y;
}
__device__ __forceinline__ float sigt(float x) {
    return fmaf(0.5f, tanha(0.5f * x), 0.5f);
}

// ---------------- GEMM 128x64 tiles ----------------
__global__ __launch_bounds__(256) void gemm128(
    const float* __restrict__ A1, const float* __restrict__ A2,
    int Ksplit, int K,
    const float* __restrict__ W, const float* __restrict__ b1,
    const float* __restrict__ b2, float* __restrict__ out, int N)
{
    __shared__ float As[16][128];
    __shared__ float Bs[16][64];
    const int m0 = blockIdx.x * 128, n0 = blockIdx.y * 64;
    const int tid = threadIdx.x;
    const int tx = tid & 15, ty = tid >> 4;
    const int lmA = tid & 127, khA = (tid >> 7) * 8;
    const int lnB = tid & 63,  kB  = (tid >> 6) * 4;
    const int K2 = K - Ksplit;

    float acc[8][4];
#pragma unroll
    for (int i = 0; i < 8; i++)
#pragma unroll
        for (int j = 0; j < 4; j++) acc[i][j] = 0.f;

    for (int k0 = 0; k0 < K; k0 += 16) {
        {
            int m = m0 + lmA;
#pragma unroll
            for (int half = 0; half < 2; half++) {
                int off = khA + half * 4;
                int kg = k0 + off;
                float4 v;
                if (kg < Ksplit) v = *(const float4*)(A1 + (size_t)m * Ksplit + kg);
                else             v = *(const float4*)(A2 + (size_t)m * K2 + (kg - Ksplit));
                As[off + 0][lmA] = v.x; As[off + 1][lmA] = v.y;
                As[off + 2][lmA] = v.z; As[off + 3][lmA] = v.w;
            }
            int n = n0 + lnB;
            float4 wv = *(const float4*)(W + (size_t)n * K + k0 + kB);
            Bs[kB + 0][lnB] = wv.x; Bs[kB + 1][lnB] = wv.y;
            Bs[kB + 2][lnB] = wv.z; Bs[kB + 3][lnB] = wv.w;
        }
        __syncthreads();
#pragma unroll
        for (int kk = 0; kk < 16; kk++) {
            float4 a0 = *(const float4*)&As[kk][ty * 8];
            float4 a1 = *(const float4*)&As[kk][ty * 8 + 4];
            float4 b  = *(const float4*)&Bs[kk][tx * 4];
            float av[8] = {a0.x, a0.y, a0.z, a0.w, a1.x, a1.y, a1.z, a1.w};
#pragma unroll
            for (int i = 0; i < 8; i++) {
                acc[i][0] = fmaf(av[i], b.x, acc[i][0]);
                acc[i][1] = fmaf(av[i], b.y, acc[i][1]);
                acc[i][2] = fmaf(av[i], b.z, acc[i][2]);
                acc[i][3] = fmaf(av[i], b.w, acc[i][3]);
            }
        }
        __syncthreads();
    }

    float bias[4];
#pragma unroll
    for (int j = 0; j < 4; j++) {
        int n = n0 + tx * 4 + j;
        bias[j] = b1[n] + (b2 ? b2[n] : 0.f);
    }
#pragma unroll
    for (int i = 0; i < 8; i++) {
        int m = m0 + ty * 8 + i;
        float4 r = make_float4(acc[i][0] + bias[0], acc[i][1] + bias[1],
                               acc[i][2] + bias[2], acc[i][3] + bias[3]);
        *(float4*)(out + (size_t)m * N + n0 + tx * 4) = r;
    }
}

// ---------------- conv1d(K=5,same) + BN + SiLU ----------------
__global__ __launch_bounds__(256, 1) void conv_bn_silu(
    const float* __restrict__ x, const float* __restrict__ cw,
    const float* __restrict__ cb, const float* __restrict__ bg,
    const float* __restrict__ bnb, const float* __restrict__ bmean,
    const float* __restrict__ bvar)
{
    extern __shared__ float sm[];
    float* xs = sm;              // [36][64]
    float* ws = sm + 36 * 64;    // [64][321]
    const int b = blockIdx.z;
    const int t0 = blockIdx.x * 32;
    const int ocb = blockIdx.y * 64;
    const int tid = threadIdx.x;

    for (int idx = tid; idx < 36 * 64; idx += 256) {
        int tr = idx >> 6, i = idx & 63;
        int tg = t0 + tr - 2;
        xs[idx] = (tg >= 0 && tg < Tq) ? x[((size_t)b * Tq + tg) * INq + i] : 0.f;
    }
    for (int idx = tid; idx < 64 * 320; idx += 256) {
        int o = idx / 320, ik = idx % 320;
        ws[o * 321 + ik] = cw[(size_t)(ocb + o) * 320 + ik];
    }
    __syncthreads();

    const int o = tid & 63, gq = tid >> 6;
    const int tb = gq * 8;
    float acc[8];
#pragma unroll
    for (int t = 0; t < 8; t++) acc[t] = 0.f;

    for (int i = 0; i < 64; i++) {
        float xv[12];
#pragma unroll
        for (int j = 0; j < 12; j++) xv[j] = xs[(tb + j) * 64 + i];
#pragma unroll
        for (int k = 0; k < 5; k++) {
            float wv = ws[o * 321 + i * 5 + k];
#pragma unroll
            for (int t = 0; t < 8; t++) acc[t] = fmaf(xv[t + k], wv, acc[t]);
        }
    }
    const int oc = ocb + o;
    float scl = rsqrtf(bvar[oc] + EPSq) * bg[oc];
    float sh = bnb[oc] - bmean[oc] * scl;
    float cbv = cb[oc];
#pragma unroll
    for (int t = 0; t < 8; t++) {
        float y = (acc[t] + cbv) * scl + sh;
        g_cv[((size_t)b * Tq + t0 + tb + t) * Hq + oc] = y / (1.f + __expf(-y));
    }
}

// ---------------- mbarrier / st.async helpers ----------------
#define MBAR_WAIT_ACQ_CLUSTER(addr, par) do {                                    \
    unsigned _done;                                                              \
    asm volatile("{\n\t.reg .pred P;\n\t"                                        \
        "mbarrier.try_wait.parity.acquire.cluster.shared::cta.b64 P, [%1], %2;\n\t" \
        "selp.b32 %0, 1, 0, P;\n\t}"                                             \
        : "=r"(_done) : "r"(addr), "r"(par) : "memory");                         \
    while (!_done) {                                                             \
        asm volatile("{\n\t.reg .pred P;\n\t"                                    \
            "mbarrier.try_wait.parity.acquire.cluster.shared::cta.b64 P, [%1], %2, 0x989680;\n\t" \
            "selp.b32 %0, 1, 0, P;\n\t}"                                         \
            : "=r"(_done) : "r"(addr), "r"(par) : "memory");                     \
    }                                                                            \
} while (0)

#define MBAR_ARM(addr, bytes) \
    asm volatile("mbarrier.arrive.expect_tx.shared.b64 _, [%0], %1;"             \
                 :: "r"(addr), "r"(bytes) : "memory")

#define ST_ASYNC_V4(daddr, r0, r1, r2, r3, mbaraddr) \
    asm volatile("st.async.weak.shared::cluster.mbarrier::complete_tx::bytes.v4.b32 " \
                 "[%0], {%1, %2, %3, %4}, [%5];"                                 \
                 :: "r"(daddr), "r"(r0), "r"(r1), "r"(r2), "r"(r3),              \
                    "r"(mbaraddr) : "memory")

__device__ __forceinline__ uint32_t smem_u32(const void* p) {
    uint32_t a;
    asm("{ .reg .u64 t; cvta.to.shared.u64 t, %1; cvt.u32.u64 %0, t; }"
        : "=r"(a) : "l"(p));
    return a;
}
__device__ __forceinline__ uint32_t mapa_u32(uint32_t a, int r) {
    uint32_t o;
    asm("mapa.shared::cluster.u32 %0, %1, %2;" : "=r"(o) : "r"(a), "r"(r));
    return o;
}

// ---------------- LSTM scan: 4 clusters x 8 CTAs, one batch per cluster --------
// Register-resident packed weights; warp-local gates (MUFU.TANH);
// h broadcast: per warp, lanes 0-7 each send ONE st.async.v4.b32 (16B = the
// warp's 4 units) to dest CTA = lane id. 64 messages per dest per step.
__global__ void __cluster_dims__(8, 1, 1) __launch_bounds__(256, 1) lstm_scan(
    const float* __restrict__ gx, const float* __restrict__ w_hh,
    float* __restrict__ h_out)
{
    __shared__ alignas(16) float h2s[2][256];
    __shared__ alignas(16) unsigned long long mbars[2];

    cg::cluster_group cluster = cg::this_cluster();
    const int rank  = (int)cluster.block_rank();
    const int batch = blockIdx.x >> 3;
    const int tid = threadIdx.x;
    const int w = tid >> 5, l = tid & 31;
    const int v  = l & 3;
    const int g  = (l >> 2) & 3;
    const int kh = l >> 4;
    const int gunit = rank * 32 + w * 4 + v;     // global hidden unit 0..255
    const int row = g * Hq + gunit;              // gate row 0..1023

    // this thread's 128 weights, packed as 64 x f32x2 (pairs along k)
    unsigned long long wreg[64];
    {
        const ulonglong2* wp = (const ulonglong2*)(w_hh + (size_t)row * Hq + (kh << 7));
#pragma unroll
        for (int i = 0; i < 32; i++) {
            ulonglong2 t2 = wp[i];
            wreg[2 * i]     = t2.x;
            wreg[2 * i + 1] = t2.y;
        }
    }

    if (tid < 256) { h2s[0][tid] = 0.f; h2s[1][tid] = 0.f; }

    const uint32_t mb0 = smem_u32(&mbars[0]);
    const uint32_t mb1 = smem_u32(&mbars[1]);
    if (tid == 0) {
        asm volatile("mbarrier.init.shared.b64 [%0], 1;" :: "r"(mb0) : "memory");
        asm volatile("mbarrier.init.shared.b64 [%0], 1;" :: "r"(mb1) : "memory");
        // arm step 1 (mbars[1]) and step 2 (mbars[0]); each phase = 1024 bytes
        MBAR_ARM(mb1, 1024);
        MBAR_ARM(mb0, 1024);
    }

    // dest addresses: lane l (l<8) sends this warp's 4-unit block to CTA l
    const uint32_t h0_local = smem_u32(&h2s[0][0]);
    const int dest = l & 7;
    uint32_t peer_h[2], peer_mb[2];
    {
        uint32_t base = mapa_u32(h0_local, dest);
        uint32_t blk = (uint32_t)((rank * 32 + w * 4) * 4);   // 16B-aligned
        peer_h[0] = base + blk;
        peer_h[1] = base + 1024u + blk;
        peer_mb[0] = mapa_u32(mb0, dest);
        peer_mb[1] = mapa_u32(mb1, dest);
    }

    cluster.sync();

    const float* gx_row = gx + (size_t)batch * Tq * G4q + row;
    const bool write_out = ((l >> 2) == rank);   // 4 lanes/warp write h_out
    const bool sender = (l < 8);
    float c0 = 0.f;
    float cur = gx_row[0];

    for (int t = 0; t < Tq; t++) {
        // prefetch next-step gx before waiting (hides DRAM latency)
        float nxt = 0.f;
        if (t + 1 < Tq) nxt = gx_row[(size_t)(t + 1) * G4q];

        if (t > 0) {
            const uint32_t mb = (t & 1) ? mb1 : mb0;
            unsigned par = (unsigned)(((t >> 1) + ((t & 1) ^ 1)) & 1);
            MBAR_WAIT_ACQ_CLUSTER(mb, par);
            // re-arm for step t+2 (safe: arm precedes this CTA's h(t+1) sends,
            // and producers need all h(t+1) before storing t+2 data here)
            if (tid == 0 && t + 2 < Tq) MBAR_ARM(mb, 1024);
        }
        const int p = t & 1;
        const ulonglong2* hb2 = (const ulonglong2*)&h2s[p][kh << 7];

        // matvec: 64 packed f32x2 FMAs, 4 independent chains
        unsigned long long acc0 = 0ull, acc1 = 0ull, acc2 = 0ull, acc3 = 0ull;
#pragma unroll
        for (int i = 0; i < 32; i += 2) {
            ulonglong2 hv0 = hb2[i];
            ulonglong2 hv1 = hb2[i + 1];
            FMA_F32X2(acc0, wreg[2 * i + 0], hv0.x, acc0);
            FMA_F32X2(acc1, wreg[2 * i + 1], hv0.y, acc1);
            FMA_F32X2(acc2, wreg[2 * i + 2], hv1.x, acc2);
            FMA_F32X2(acc3, wreg[2 * i + 3], hv1.y, acc3);
        }
        float partial = (hsum_f32x2(acc0) + hsum_f32x2(acc1))
                      + (hsum_f32x2(acc2) + hsum_f32x2(acc3));
        // combine k-halves (lanes l and l^16 hold the two halves of same row)
        float sum = partial + __shfl_xor_sync(0xFFFFFFFFu, partial, 16);
        sum += cur;   // gx for this row

        // gather the 4 gate sums of unit v (lanes v, v+4, v+8, v+12)
        float si = __shfl_sync(0xFFFFFFFFu, sum, v);
        float sf = __shfl_sync(0xFFFFFFFFu, sum, v + 4);
        float sg = __shfl_sync(0xFFFFFFFFu, sum, v + 8);
        float so = __shfl_sync(0xFFFFFFFFu, sum, v + 12);

        // every lane redundantly computes h(unit v) — single-MUFU tanh path
        c0 = sigt(sf) * c0 + sigt(si) * tanha(sg);
        float hnew = sigt(so) * tanha(c0);

        if (write_out)
            h_out[((size_t)batch * Tq + t) * Hq + gunit] = hnew;

        if (t + 1 < Tq) {
            // broadcast the warp's 4 unit values to all lanes
            unsigned hu = __float_as_uint(hnew);
            unsigned f0 = __shfl_sync(0xFFFFFFFFu, hu, 0);
            unsigned f1 = __shfl_sync(0xFFFFFFFFu, hu, 1);
            unsigned f2 = __shfl_sync(0xFFFFFFFFu, hu, 2);
            unsigned f3 = __shfl_sync(0xFFFFFFFFu, hu, 3);
            if (sender) {
                const int q = (t + 1) & 1;
                ST_ASYNC_V4(peer_h[q], f0, f1, f2, f3, peer_mb[q]);
            }
        }
        cur = nxt;
    }
    cluster.sync();
}

// ---------------- no-op spacer (aligns ncu -s 5 onto scan1) ----------------
__global__ void noop_k() {}

// ---------------- attention (last query row only) ----------------
__global__ __launch_bounds__(256) void attn_last(
    const float* __restrict__ qkv_w, const float* __restrict__ qkv_b)
{
    __shared__ float q[64];
    __shared__ float sc[Tq];
    __shared__ float red[256];
    __shared__ float vp[256];
    const int bh = blockIdx.x;
    const int b = bh >> 3, h = bh & 7;
    const int tid = threadIdx.x;

    if (tid < 64) {
        int row = h * 64 + tid;
        const float* wr = qkv_w + (size_t)row * Dq;
        const float* ml = g_h2 + ((size_t)b * Tq + (Tq - 1)) * Hq;
        const float* mc = g_cv + ((size_t)b * Tq + (Tq - 1)) * Hq;
        float acc = qkv_b[row];
        for (int k = 0; k < 256; k++) acc = fmaf(ml[k], wr[k], acc);
        for (int k = 0; k < 256; k++) acc = fmaf(mc[k], wr[256 + k], acc);
        q[tid] = acc * 0.125f;
    }
    __syncthreads();

    float lmax = -1e30f;
    for (int t = tid; t < Tq; t += 256) {
        const float4* kp = (const float4*)(g_kv + ((size_t)b * Tq + t) * G4q + h * 64);
        float s = 0.f;
#pragma unroll
        for (int d4 = 0; d4 < 16; d4++) {
            float4 kk = kp[d4];
            float4 qq = ((const float4*)q)[d4];
            s += kk.x * qq.x + kk.y * qq.y + kk.z * qq.z + kk.w * qq.w;
        }
        sc[t] = s;
        lmax = fmaxf(lmax, s);
    }
    red[tid] = lmax; __syncthreads();
    for (int s2 = 128; s2 > 0; s2 >>= 1) {
        if (tid < s2) red[tid] = fmaxf(red[tid], red[tid + s2]);
        __syncthreads();
    }
    float m = red[0];
    __syncthreads();

    float lsum = 0.f;
    for (int t = tid; t < Tq; t += 256) {
        float pe = __expf(sc[t] - m);
        sc[t] = pe;
        lsum += pe;
    }
    red[tid] = lsum; __syncthreads();
    for (int s2 = 128; s2 > 0; s2 >>= 1) {
        if (tid < s2) red[tid] += red[tid + s2];
        __syncthreads();
    }
    float denom = red[0];
    __syncthreads();

    const int d = tid & 63, gg = tid >> 6;
    float acc = 0.f;
    for (int t = gg * 512; t < (gg + 1) * 512; t++)
        acc = fmaf(sc[t], g_kv[((size_t)b * Tq + t) * G4q + 512 + h * 64 + d], acc);
    vp[tid] = acc; __syncthreads();
    if (tid < 64) {
        float o = (vp[tid] + vp[64 + tid] + vp[128 + tid] + vp[192 + tid]) / denom;
        g_at[b * Dq + h * 64 + tid] = o;
    }
}

// ---------------- head ----------------
__global__ __launch_bounds__(512) void head_kernel(
    const float* __restrict__ pw, const float* __restrict__ pb,
    const float* __restrict__ lng, const float* __restrict__ lnb,
    const float* __restrict__ f1w, const float* __restrict__ f1b,
    const float* __restrict__ f2w, const float* __restrict__ f2b,
    float* __restrict__ out)
{
    __shared__ float a[Dq], zn[Dq], z2[Hq], red[512];
    const int b = blockIdx.x, tid = threadIdx.x;
    a[tid] = g_at[b * Dq + tid];
    __syncthreads();

    float acc = pb[tid];
    const float* wr = pw + (size_t)tid * Dq;
    for (int k = 0; k < Dq; k++) acc = fmaf(a[k], wr[k], acc);
    float mrg = (tid < 256) ? g_h2[((size_t)b * Tq + Tq - 1) * Hq + tid]
                            : g_cv[((size_t)b * Tq + Tq - 1) * Hq + tid - 256];
    float z = acc + mrg;

    red[tid] = z; __syncthreads();
    for (int s = 256; s > 0; s >>= 1) {
        if (tid < s) red[tid] += red[tid + s];
        __syncthreads();
    }
    float mu = red[0] / 512.f;
    __syncthreads();
    float dv = z - mu;
    red[tid] = dv * dv; __syncthreads();
    for (int s = 256; s > 0; s >>= 1) {
        if (tid < s) red[tid] += red[tid + s];
        __syncthreads();
    }
    float var = red[0] / 512.f;
    __syncthreads();

    zn[tid] = dv * rsqrtf(var + EPSq) * lng[tid] + lnb[tid];
    __syncthreads();

    if (tid < 256) {
        float a2 = f1b[tid];
        const float* w1 = f1w + (size_t)tid * Dq;
        for (int k = 0; k < Dq; k++) a2 = fmaf(zn[k], w1[k], a2);
        z2[tid] = a2 / (1.f + expf(-a2));
    }
    __syncthreads();

    if (tid < 3) {
        float lg = f2b[tid];
        const float* w2 = f2w + tid * 256;
        for (int j = 0; j < 256; j++) lg = fmaf(z2[j], w2[j], lg);
        if (tid == 0)      out[b]     = tanhf(lg);
        else if (tid == 1) out[4 + b] = (lg > 20.f) ? lg : log1pf(expf(lg));
        else               out[8 + b] = 1.f / (1.f + expf(-lg));
    }
}

// ---------------- launch ----------------
extern "C" void kernel_launch(void* const* d_in, const int* in_sizes, int n_in,
                              void* d_out, int out_size) {
    const float* x     = (const float*)d_in[0];
    const float* wih0  = (const float*)d_in[1];
    const float* whh0  = (const float*)d_in[2];
    const float* bih0  = (const float*)d_in[3];
    const float* bhh0  = (const float*)d_in[4];
    const float* wih1  = (const float*)d_in[5];
    const float* whh1  = (const float*)d_in[6];
    const float* bih1  = (const float*)d_in[7];
    const float* bhh1  = (const float*)d_in[8];
    const float* cw    = (const float*)d_in[9];
    const float* cb    = (const float*)d_in[10];
    const float* bng   = (const float*)d_in[11];
    const float* bnb   = (const float*)d_in[12];
    const float* bnm   = (const float*)d_in[13];
    const float* bnv   = (const float*)d_in[14];
    const float* qkvw  = (const float*)d_in[15];
    const float* qkvb  = (const float*)d_in[16];
    const float* pw    = (const float*)d_in[17];
    const float* pbv   = (const float*)d_in[18];
    const float* lng   = (const float*)d_in[19];
    const float* lnb   = (const float*)d_in[20];
    const float* f1w   = (const float*)d_in[21];
    const float* f1b   = (const float*)d_in[22];
    const float* f2w   = (const float*)d_in[23];
    const float* f2b   = (const float*)d_in[24];
    float* out = (float*)d_out;

    float *gx0, *gx1, *h1, *h2, *cv, *kv;
    cudaGetSymbolAddress((void**)&gx0, g_gx0);
    cudaGetSymbolAddress((void**)&gx1, g_gx1);
    cudaGetSymbolAddress((void**)&h1,  g_h1);
    cudaGetSymbolAddress((void**)&h2,  g_h2);
    cudaGetSymbolAddress((void**)&cv,  g_cv);
    cudaGetSymbolAddress((void**)&kv,  g_kv);

    const int conv_smem = (36 * 64 + 64 * 321) * 4;
    cudaFuncSetAttribute(conv_bn_silu, cudaFuncAttributeMaxDynamicSharedMemorySize, conv_smem);

    // 0: gx0 = x @ w_ih0^T + b_ih0 + b_hh0
    gemm128<<<dim3(64, 16), 256>>>(x, nullptr, 64, 64, wih0, bih0, bhh0, gx0, G4q);
    // 1: conv branch (independent of LSTM)
    conv_bn_silu<<<dim3(64, 4, 4), 256, conv_smem>>>(x, cw, cb, bng, bnb, bnm, bnv);
    // 2: layer-0 scan: 4 clusters (one per batch) x 8 CTAs
    lstm_scan<<<32, 256>>>(gx0, whh0, h1);
    // 3: gx1 = h1 @ w_ih1^T + b_ih1 + b_hh1
    gemm128<<<dim3(64, 16), 256>>>(h1, nullptr, 256, 256, wih1, bih1, bhh1, gx1, G4q);
    // 4: spacer so ncu (-s 5 -c 1) captures the scan next
    noop_k<<<1, 32>>>();
    // 5: layer-1 scan  <-- profiled launch
    lstm_scan<<<32, 256>>>(gx1, whh1, h2);
    // 6: kv = merged @ qkv_w[512:1536]^T + qkv_b[512:1536]
    gemm128<<<dim3(64, 16), 256>>>(h2, cv, 256, 512, qkvw + 512 * 512, qkvb + 512,
                                   nullptr, kv, G4q);
    // 7: attention (last row only)
    attn_last<<<32, 256>>>(qkvw, qkvb);
    // 8: head
    head_kernel<<<4, 512>>>(pw, pbv, lng, lnb, f1w, f1b, f2w, f2b, out);
}